// round 1
// baseline (speedup 1.0000x reference)
#include <cuda_runtime.h>
#include <cstdint>

#define DEVINLINE __device__ __forceinline__

constexpr int B_  = 4;
constexpr int T_  = 2048;
constexpr int D_  = 1024;
constexpr int H_  = 16;
constexpr int HD_ = 64;
constexpr int M1  = B_ * T_;      // 8192 tokens
constexpr int N_QKV = 3 * D_;     // 3072

// ---- scratch (static __device__ arrays; no allocation allowed) ----
__device__ float g_Q[(size_t)B_ * H_ * T_ * HD_];
__device__ float g_K[(size_t)B_ * H_ * T_ * HD_];
__device__ float g_V[(size_t)B_ * H_ * T_ * HD_];
__device__ float g_attn[(size_t)M1 * D_];

DEVINLINE float ex2f(float x) {
    float y;
    asm("ex2.approx.ftz.f32 %0, %1;" : "=f"(y) : "f"(x));
    return y;
}

// =====================================================================
// GEMM: C[m,n] = sum_k A[m,k] * W[n,k]   (both operands K-contiguous, "NT")
// Block tile 128x128, K-tile 16, 256 threads, 8x8 micro (2x(4+4) split).
// MODE 0: A = x,    epilogue scatters into g_Q/g_K/g_V  ([B,H,T,hd])
// MODE 1: A = g_attn, epilogue writes Cout + bias       ([B,T,D])
// =====================================================================
template <int MODE>
__global__ __launch_bounds__(256, 2)
void gemm_kernel(const float* __restrict__ Ain, const float* __restrict__ W,
                 const float* __restrict__ bias, float* __restrict__ Cout)
{
    constexpr int KT  = 16;
    constexpr int LDS = 132;  // 128 + 4 pad: keeps float4 alignment, 2-way store conflicts only
    __shared__ float As[KT][LDS];
    __shared__ float Bs[KT][LDS];

    const float* A = (MODE == 1) ? (const float*)g_attn : Ain;

    const int tid = threadIdx.x;
    const int ty  = tid >> 4;        // 0..15
    const int tx  = tid & 15;        // 0..15
    const int bm  = blockIdx.y * 128;
    const int bn  = blockIdx.x * 128;

    float acc[8][8];
#pragma unroll
    for (int i = 0; i < 8; ++i)
#pragma unroll
        for (int j = 0; j < 8; ++j) acc[i][j] = 0.f;

    const int lr = tid >> 2;          // 0..63 : row within half-tile
    const int lq = (tid & 3) << 2;    // 0,4,8,12 : k-offset of float4

    const float* Ap0 = A + (long)(bm + lr) * D_ + lq;
    const float* Ap1 = Ap0 + (long)64 * D_;
    const float* Wp0 = W + (long)(bn + lr) * D_ + lq;
    const float* Wp1 = Wp0 + (long)64 * D_;

    for (int k0 = 0; k0 < D_; k0 += KT) {
        float4 a0 = *(const float4*)(Ap0 + k0);
        float4 a1 = *(const float4*)(Ap1 + k0);
        float4 b0 = *(const float4*)(Wp0 + k0);
        float4 b1 = *(const float4*)(Wp1 + k0);
        // transposed store: As[k][m]
        As[lq + 0][lr] = a0.x; As[lq + 1][lr] = a0.y;
        As[lq + 2][lr] = a0.z; As[lq + 3][lr] = a0.w;
        As[lq + 0][lr + 64] = a1.x; As[lq + 1][lr + 64] = a1.y;
        As[lq + 2][lr + 64] = a1.z; As[lq + 3][lr + 64] = a1.w;
        Bs[lq + 0][lr] = b0.x; Bs[lq + 1][lr] = b0.y;
        Bs[lq + 2][lr] = b0.z; Bs[lq + 3][lr] = b0.w;
        Bs[lq + 0][lr + 64] = b1.x; Bs[lq + 1][lr + 64] = b1.y;
        Bs[lq + 2][lr + 64] = b1.z; Bs[lq + 3][lr + 64] = b1.w;
        __syncthreads();

#pragma unroll
        for (int k = 0; k < KT; ++k) {
            float a[8], b[8];
            *(float4*)&a[0] = *(const float4*)&As[k][4 * ty];
            *(float4*)&a[4] = *(const float4*)&As[k][64 + 4 * ty];
            *(float4*)&b[0] = *(const float4*)&Bs[k][4 * tx];
            *(float4*)&b[4] = *(const float4*)&Bs[k][64 + 4 * tx];
#pragma unroll
            for (int i = 0; i < 8; ++i)
#pragma unroll
                for (int j = 0; j < 8; ++j)
                    acc[i][j] = fmaf(a[i], b[j], acc[i][j]);
        }
        __syncthreads();
    }

    if (MODE == 0) {
        // scatter QKV into [B,H,T,hd] layout
#pragma unroll
        for (int i = 0; i < 8; ++i) {
            const int gm = bm + ((i & 4) << 4) + 4 * ty + (i & 3);
            const int bb = gm >> 11;          // / T_
            const int t  = gm & (T_ - 1);
#pragma unroll
            for (int jq = 0; jq < 2; ++jq) {
                const int gn   = bn + (jq << 6) + 4 * tx;
                const int part = gn >> 10;    // 0=Q 1=K 2=V
                const int c    = gn & 1023;
                const int h    = c >> 6;
                const int d    = c & 63;
                float* dst = (part == 0) ? g_Q : (part == 1) ? g_K : g_V;
                float4 v = make_float4(acc[i][4 * jq + 0], acc[i][4 * jq + 1],
                                       acc[i][4 * jq + 2], acc[i][4 * jq + 3]);
                *(float4*)&dst[(((long)(bb * H_ + h) * T_ + t) << 6) + d] = v;
            }
        }
    } else {
#pragma unroll
        for (int i = 0; i < 8; ++i) {
            const int gm = bm + ((i & 4) << 4) + 4 * ty + (i & 3);
#pragma unroll
            for (int jq = 0; jq < 2; ++jq) {
                const int gn = bn + (jq << 6) + 4 * tx;
                float4 bv = *(const float4*)&bias[gn];
                float4 v  = make_float4(acc[i][4 * jq + 0] + bv.x,
                                        acc[i][4 * jq + 1] + bv.y,
                                        acc[i][4 * jq + 2] + bv.z,
                                        acc[i][4 * jq + 3] + bv.w);
                *(float4*)&Cout[(long)gm * D_ + gn] = v;
            }
        }
    }
}

// =====================================================================
// Flash attention, fp32, causal. One block per (b,h, 64-row q-tile).
// Swizzled smem: element (r,c) -> r*64 + 4*(((c>>2)^(r>>2))&15) + (c&3).
// Makes every LDS.128 pattern (row-broadcast AND 4-strided-row) conflict-free.
// P tile overlays the K tile buffer -> 48KB static smem.
// =====================================================================
DEVINLINE int sw_(int r, int c) {
    return (r << 6) + ((((c >> 2) ^ (r >> 2)) & 15) << 2) + (c & 3);
}

__global__ __launch_bounds__(256, 2)
void flash_attn_kernel()
{
    __shared__ float Qs[64 * 64];
    __shared__ float KPs[64 * 64];   // K tile, overlaid by P tile
    __shared__ float Vs[64 * 64];

    const int tid = threadIdx.x;
    const int ty  = tid >> 4;        // 0..15 : 4 q-rows
    const int tx  = tid & 15;        // 0..15 : 4 cols
    const int qt  = blockIdx.x;      // q tile 0..31
    const int bh  = blockIdx.y;      // 0..63

    const float* Qg = g_Q + (long)bh * T_ * HD_;
    const float* Kg = g_K + (long)bh * T_ * HD_;
    const float* Vg = g_V + (long)bh * T_ * HD_;

    const float NEG_INF = __int_as_float(0xff800000);
    const float SC = 0.18033688011112042385f;   // (1/sqrt(64)) * log2(e)

    // load Q tile (64x64) into swizzled smem
#pragma unroll
    for (int u = 0; u < 4; ++u) {
        int idx = tid + (u << 8);
        int r = idx >> 4, c = (idx & 15) << 2;
        *(float4*)&Qs[sw_(r, c)] = *(const float4*)(Qg + ((long)((qt << 6) + r) << 6) + c);
    }

    float acc[4][4];
#pragma unroll
    for (int i = 0; i < 4; ++i)
#pragma unroll
        for (int j = 0; j < 4; ++j) acc[i][j] = 0.f;
    float mrow[4], lrow[4];
#pragma unroll
    for (int i = 0; i < 4; ++i) { mrow[i] = NEG_INF; lrow[i] = 0.f; }

    for (int kt = 0; kt <= qt; ++kt) {
        __syncthreads();   // previous O-GEMM reads of KPs/Vs complete
#pragma unroll
        for (int u = 0; u < 4; ++u) {
            int idx = tid + (u << 8);
            int r = idx >> 4, c = (idx & 15) << 2;
            long goff = ((long)((kt << 6) + r) << 6) + c;
            *(float4*)&KPs[sw_(r, c)] = *(const float4*)(Kg + goff);
            *(float4*)&Vs[sw_(r, c)]  = *(const float4*)(Vg + goff);
        }
        __syncthreads();

        // S = Q K^T  (4x4 per thread)
        float s[4][4];
#pragma unroll
        for (int i = 0; i < 4; ++i)
#pragma unroll
            for (int j = 0; j < 4; ++j) s[i][j] = 0.f;
#pragma unroll
        for (int d0 = 0; d0 < 64; d0 += 4) {
            float aq[4][4], bk[4][4];
#pragma unroll
            for (int i = 0; i < 4; ++i)
                *(float4*)&aq[i][0] = *(const float4*)&Qs[sw_(4 * ty + i, d0)];
#pragma unroll
            for (int j = 0; j < 4; ++j)
                *(float4*)&bk[j][0] = *(const float4*)&KPs[sw_(4 * tx + j, d0)];
#pragma unroll
            for (int i = 0; i < 4; ++i)
#pragma unroll
                for (int j = 0; j < 4; ++j)
#pragma unroll
                    for (int e = 0; e < 4; ++e)
                        s[i][j] = fmaf(aq[i][e], bk[j][e], s[i][j]);
        }
        __syncthreads();   // all K reads done; KPs becomes P

        const bool diag = (kt == qt);
#pragma unroll
        for (int i = 0; i < 4; ++i) {
            const int gm = (qt << 6) + 4 * ty + i;
#pragma unroll
            for (int j = 0; j < 4; ++j) {
                float v = s[i][j] * SC;
                if (diag) {
                    int gn = (kt << 6) + 4 * tx + j;
                    if (gn > gm) v = NEG_INF;
                }
                s[i][j] = v;
            }
            float rmax = fmaxf(fmaxf(s[i][0], s[i][1]), fmaxf(s[i][2], s[i][3]));
#pragma unroll
            for (int off = 8; off >= 1; off >>= 1)
                rmax = fmaxf(rmax, __shfl_xor_sync(0xffffffffu, rmax, off));
            const float mnew  = fmaxf(mrow[i], rmax);
            const float alpha = ex2f(mrow[i] - mnew);   // exp2(-inf)=0 on first tile
            mrow[i] = mnew;
            float rsum = 0.f;
#pragma unroll
            for (int j = 0; j < 4; ++j) {
                float p = ex2f(s[i][j] - mnew);
                s[i][j] = p;
                rsum += p;
            }
#pragma unroll
            for (int off = 8; off >= 1; off >>= 1)
                rsum += __shfl_xor_sync(0xffffffffu, rsum, off);
            lrow[i] = lrow[i] * alpha + rsum;
#pragma unroll
            for (int j = 0; j < 4; ++j) acc[i][j] *= alpha;
            *(float4*)&KPs[sw_(4 * ty + i, 4 * tx)] =
                make_float4(s[i][0], s[i][1], s[i][2], s[i][3]);
        }
        __syncthreads();

        // O += P V
#pragma unroll
        for (int j0 = 0; j0 < 64; j0 += 4) {
            float pv[4][4], vv[4][4];
#pragma unroll
            for (int i = 0; i < 4; ++i)
                *(float4*)&pv[i][0] = *(const float4*)&KPs[sw_(4 * ty + i, j0)];
#pragma unroll
            for (int e = 0; e < 4; ++e)
                *(float4*)&vv[e][0] = *(const float4*)&Vs[sw_(j0 + e, 4 * tx)];
#pragma unroll
            for (int i = 0; i < 4; ++i)
#pragma unroll
                for (int e = 0; e < 4; ++e)
#pragma unroll
                    for (int j = 0; j < 4; ++j)
                        acc[i][j] = fmaf(pv[i][e], vv[e][j], acc[i][j]);
        }
    }

    // epilogue: O /= l, write to g_attn in [B,T,D] layout (proj GEMM input)
    const int b = bh >> 4, h = bh & 15;
#pragma unroll
    for (int i = 0; i < 4; ++i) {
        const float inv = 1.f / lrow[i];
        const int t = (qt << 6) + 4 * ty + i;
        float4 o = make_float4(acc[i][0] * inv, acc[i][1] * inv,
                               acc[i][2] * inv, acc[i][3] * inv);
        *(float4*)&g_attn[((long)(b * T_ + t) << 10) + (h << 6) + (tx << 2)] = o;
    }
}

// =====================================================================
extern "C" void kernel_launch(void* const* d_in, const int* in_sizes, int n_in,
                              void* d_out, int out_size)
{
    const float* x     = (const float*)d_in[0];
    const float* Wqkv  = (const float*)d_in[1];
    const float* Wproj = (const float*)d_in[2];
    const float* bproj = (const float*)d_in[3];
    float* out = (float*)d_out;

    (void)in_sizes; (void)n_in; (void)out_size;

    dim3 gq(N_QKV / 128, M1 / 128);   // 24 x 64
    gemm_kernel<0><<<gq, 256>>>(x, Wqkv, nullptr, nullptr);

    dim3 ga(T_ / 64, B_ * H_);        // 32 x 64
    flash_attn_kernel<<<ga, 256>>>();

    dim3 gp(D_ / 128, M1 / 128);      // 8 x 64
    gemm_kernel<1><<<gp, 256>>>(nullptr, Wproj, bproj, out);
}

// round 3
// speedup vs baseline: 2.3423x; 2.3423x over previous
#include <cuda_runtime.h>
#include <cuda_bf16.h>
#include <cstdint>

#define DEVINLINE __device__ __forceinline__

constexpr int B_  = 4;
constexpr int T_  = 2048;
constexpr int D_  = 1024;
constexpr int H_  = 16;
constexpr int HD_ = 64;
constexpr int M1  = B_ * T_;      // 8192
constexpr int N_QKV = 3 * D_;     // 3072

// ---- scratch ----
__device__ float g_Q[(size_t)B_ * H_ * T_ * HD_];
__device__ float g_K[(size_t)B_ * H_ * T_ * HD_];
__device__ float g_V[(size_t)B_ * H_ * T_ * HD_];
__device__ float g_attn[(size_t)M1 * D_];

// =====================================================================
// helpers (arch-portable PTX only: mma.sync is sm_80 baseline)
// =====================================================================
DEVINLINE float ex2f(float x) {
    float y; asm("ex2.approx.ftz.f32 %0, %1;" : "=f"(y) : "f"(x)); return y;
}

DEVINLINE uint32_t packbf(float lo_elem, float hi_elem) {
    // low 16 bits <- lo_elem, high 16 bits <- hi_elem (both RN)
    uint32_t r;
    asm("cvt.rn.bf16x2.f32 %0, %1, %2;" : "=r"(r) : "f"(hi_elem), "f"(lo_elem));
    return r;
}

// split pair (x,y) into bf16 hi pair + bf16 lo (residual) pair
DEVINLINE void split2(float x, float y, uint32_t& hi, uint32_t& lo) {
    hi = packbf(x, y);
    float hx = __uint_as_float(hi << 16);
    float hy = __uint_as_float(hi & 0xffff0000u);
    lo = packbf(x - hx, y - hy);
}

DEVINLINE void mma16816(float c[4], const uint32_t a[4], const uint32_t b[2]) {
    asm volatile(
        "mma.sync.aligned.m16n8k16.row.col.f32.bf16.bf16.f32 "
        "{%0,%1,%2,%3}, {%4,%5,%6,%7}, {%8,%9}, {%0,%1,%2,%3};"
        : "+f"(c[0]), "+f"(c[1]), "+f"(c[2]), "+f"(c[3])
        : "r"(a[0]), "r"(a[1]), "r"(a[2]), "r"(a[3]), "r"(b[0]), "r"(b[1]));
}

// =====================================================================
// HMMA GEMM: C[m,n] = sum_k A[m,k]*W[n,k]; fp32 via bf16 3-term split.
// Tile 128x128x32, 8 warps (4m x 2n), warp tile 32x64.
// MODE 0: A=x, scatter into g_Q/g_K/g_V.   MODE 1: A=g_attn, out+bias.
// =====================================================================
constexpr int RS_G  = 40;              // bf16 row stride (pad 32->40): conflict-free frags
constexpr int TILEB = 128 * RS_G * 2;  // 10240 B

template <int MODE>
__global__ __launch_bounds__(256, 1)
void gemm_mma(const float* __restrict__ Ain, const float* __restrict__ W,
              const float* __restrict__ bias, float* __restrict__ Cout)
{
    __shared__ __align__(16) char sm[4 * TILEB];
    const float* A = (MODE == 1) ? (const float*)g_attn : Ain;

    const int tid = threadIdx.x, lane = tid & 31, wid = tid >> 5;
    const int g = lane >> 2, t = lane & 3;
    const int wm = wid >> 1, wn = wid & 1;
    const int bm = blockIdx.y * 128, bn = blockIdx.x * 128;

    char* Ahi = sm;
    char* Alo = sm + TILEB;
    char* Bhi = sm + 2 * TILEB;
    char* Blo = sm + 3 * TILEB;

    const int ldr = tid >> 3;         // 0..31
    const int ldc = (tid & 7) * 4;    // 0..28

    float c[2][8][4];
#pragma unroll
    for (int i = 0; i < 2; ++i)
#pragma unroll
        for (int j = 0; j < 8; ++j)
#pragma unroll
            for (int k = 0; k < 4; ++k) c[i][j][k] = 0.f;

    float4 ra[4], rb[4];

    auto ldg = [&](int k0) {
#pragma unroll
        for (int u = 0; u < 4; ++u) {
            ra[u] = *(const float4*)(A + (size_t)(bm + ldr + 32 * u) * D_ + k0 + ldc);
            rb[u] = *(const float4*)(W + (size_t)(bn + ldr + 32 * u) * D_ + k0 + ldc);
        }
    };
    auto sts = [&]() {
#pragma unroll
        for (int u = 0; u < 4; ++u) {
            const int row = ldr + 32 * u;
            uint32_t h0, l0, h1, l1;
            split2(ra[u].x, ra[u].y, h0, l0);
            split2(ra[u].z, ra[u].w, h1, l1);
            *(uint2*)(Ahi + row * 80 + ldc * 2) = make_uint2(h0, h1);
            *(uint2*)(Alo + row * 80 + ldc * 2) = make_uint2(l0, l1);
            split2(rb[u].x, rb[u].y, h0, l0);
            split2(rb[u].z, rb[u].w, h1, l1);
            *(uint2*)(Bhi + row * 80 + ldc * 2) = make_uint2(h0, h1);
            *(uint2*)(Blo + row * 80 + ldc * 2) = make_uint2(l0, l1);
        }
    };

    ldg(0); sts(); __syncthreads();

    constexpr int NT = D_ / 32;
    for (int kt = 0; kt < NT; ++kt) {
        if (kt + 1 < NT) ldg((kt + 1) * 32);
#pragma unroll
        for (int ks = 0; ks < 2; ++ks) {
            const int koff = ks * 32 + t * 4;      // bytes within row
            uint32_t ah[2][4], al[2][4];
#pragma unroll
            for (int mi = 0; mi < 2; ++mi) {
                const char* p = Ahi + (wm * 32 + mi * 16 + g) * 80 + koff;
                const char* q = Alo + (wm * 32 + mi * 16 + g) * 80 + koff;
                ah[mi][0] = *(const uint32_t*)p;
                ah[mi][1] = *(const uint32_t*)(p + 640);
                ah[mi][2] = *(const uint32_t*)(p + 16);
                ah[mi][3] = *(const uint32_t*)(p + 656);
                al[mi][0] = *(const uint32_t*)q;
                al[mi][1] = *(const uint32_t*)(q + 640);
                al[mi][2] = *(const uint32_t*)(q + 16);
                al[mi][3] = *(const uint32_t*)(q + 656);
            }
#pragma unroll
            for (int nj = 0; nj < 8; ++nj) {
                const char* p = Bhi + (wn * 64 + nj * 8 + g) * 80 + koff;
                const char* q = Blo + (wn * 64 + nj * 8 + g) * 80 + koff;
                uint32_t bh[2] = {*(const uint32_t*)p, *(const uint32_t*)(p + 16)};
                uint32_t bl[2] = {*(const uint32_t*)q, *(const uint32_t*)(q + 16)};
#pragma unroll
                for (int mi = 0; mi < 2; ++mi) {
                    mma16816(c[mi][nj], ah[mi], bh);
                    mma16816(c[mi][nj], ah[mi], bl);
                    mma16816(c[mi][nj], al[mi], bh);
                }
            }
        }
        __syncthreads();
        if (kt + 1 < NT) { sts(); __syncthreads(); }
    }

    // epilogue: c0,c1 = (row g, cols 2t,2t+1); c2,c3 = row g+8
#pragma unroll
    for (int mi = 0; mi < 2; ++mi) {
        const int r0 = bm + wm * 32 + mi * 16 + g;
        const int r1 = r0 + 8;
#pragma unroll
        for (int nj = 0; nj < 8; ++nj) {
            const int cn = bn + wn * 64 + nj * 8 + 2 * t;
            if (MODE == 0) {
                const int part = cn >> 10, ccc = cn & 1023;
                const int hh = ccc >> 6, dd = ccc & 63;
                float* dst = (part == 0) ? g_Q : (part == 1) ? g_K : g_V;
                {
                    const int bb = r0 >> 11, tt = r0 & 2047;
                    *(float2*)&dst[(((size_t)(bb * H_ + hh) * T_ + tt) << 6) + dd] =
                        make_float2(c[mi][nj][0], c[mi][nj][1]);
                }
                {
                    const int bb = r1 >> 11, tt = r1 & 2047;
                    *(float2*)&dst[(((size_t)(bb * H_ + hh) * T_ + tt) << 6) + dd] =
                        make_float2(c[mi][nj][2], c[mi][nj][3]);
                }
            } else {
                float2 bv = *(const float2*)&bias[cn];
                *(float2*)&Cout[(size_t)r0 * D_ + cn] =
                    make_float2(c[mi][nj][0] + bv.x, c[mi][nj][1] + bv.y);
                *(float2*)&Cout[(size_t)r1 * D_ + cn] =
                    make_float2(c[mi][nj][2] + bv.x, c[mi][nj][3] + bv.y);
            }
        }
    }
}

// =====================================================================
// HMMA flash attention, causal. q-tile 128 (warp w: rows w*16..+15),
// k-tile 64, hd 64. P stays in registers (C-frag -> A-frag repack).
// =====================================================================
constexpr int ARS  = 72;               // bf16 row stride (64 -> 72): conflict-free
constexpr int AQB  = 128 * ARS * 2;    // 18432
constexpr int AKB  = 64 * ARS * 2;     // 9216
constexpr int OQHI = 0, OQLO = AQB;
constexpr int OKHI = 2 * AQB, OKLO = OKHI + AKB;
constexpr int OVHI = OKLO + AKB, OVLO = OVHI + AKB;
constexpr int FA_SMEM = OVLO + AKB;    // 73728

__global__ __launch_bounds__(256, 1)
void flash_mma()
{
    extern __shared__ __align__(16) char sm[];
    const int tid = threadIdx.x, lane = tid & 31, wid = tid >> 5;
    const int g = lane >> 2, t = lane & 3;
    const int qt = blockIdx.x, bh = blockIdx.y;
    const int qbase = qt * 128;
    const int nkt = 2 * qt + 2;

    const float* Qg = g_Q + (size_t)bh * T_ * HD_;
    const float* Kg = g_K + (size_t)bh * T_ * HD_;
    const float* Vg = g_V + (size_t)bh * T_ * HD_;

    const float NEG_INF = __int_as_float(0xff800000);
    const float SC = 0.18033688011112042385f;   // log2(e)/sqrt(64)

    const int ldrq = tid >> 4;         // 0..15
    const int ldc  = (tid & 15) * 4;   // 0..60

    // ---- load Q tile once (hi/lo split) ----
#pragma unroll
    for (int u = 0; u < 8; ++u) {
        const int row = ldrq + 16 * u;
        float4 v = *(const float4*)(Qg + (size_t)(qbase + row) * HD_ + ldc);
        uint32_t h0, l0, h1, l1;
        split2(v.x, v.y, h0, l0);
        split2(v.z, v.w, h1, l1);
        *(uint2*)(sm + OQHI + row * 144 + ldc * 2) = make_uint2(h0, h1);
        *(uint2*)(sm + OQLO + row * 144 + ldc * 2) = make_uint2(l0, l1);
    }

    float4 rk[4], rv[4];
    auto ldkv = [&](int kt) {
#pragma unroll
        for (int u = 0; u < 4; ++u) {
            const int row = ldrq + 16 * u;
            rk[u] = *(const float4*)(Kg + (size_t)(kt * 64 + row) * HD_ + ldc);
            rv[u] = *(const float4*)(Vg + (size_t)(kt * 64 + row) * HD_ + ldc);
        }
    };
    auto stkv = [&]() {
#pragma unroll
        for (int u = 0; u < 4; ++u) {
            const int row = ldrq + 16 * u;
            uint32_t h0, l0, h1, l1;
            split2(rk[u].x, rk[u].y, h0, l0);
            split2(rk[u].z, rk[u].w, h1, l1);
            *(uint2*)(sm + OKHI + row * 144 + ldc * 2) = make_uint2(h0, h1);
            *(uint2*)(sm + OKLO + row * 144 + ldc * 2) = make_uint2(l0, l1);
            // V stored transposed: Vt[hd][key]
            split2(rv[u].x, rv[u].y, h0, l0);
            split2(rv[u].z, rv[u].w, h1, l1);
            *(uint16_t*)(sm + OVHI + (ldc + 0) * 144 + row * 2) = (uint16_t)(h0 & 0xffff);
            *(uint16_t*)(sm + OVHI + (ldc + 1) * 144 + row * 2) = (uint16_t)(h0 >> 16);
            *(uint16_t*)(sm + OVHI + (ldc + 2) * 144 + row * 2) = (uint16_t)(h1 & 0xffff);
            *(uint16_t*)(sm + OVHI + (ldc + 3) * 144 + row * 2) = (uint16_t)(h1 >> 16);
            *(uint16_t*)(sm + OVLO + (ldc + 0) * 144 + row * 2) = (uint16_t)(l0 & 0xffff);
            *(uint16_t*)(sm + OVLO + (ldc + 1) * 144 + row * 2) = (uint16_t)(l0 >> 16);
            *(uint16_t*)(sm + OVLO + (ldc + 2) * 144 + row * 2) = (uint16_t)(l1 & 0xffff);
            *(uint16_t*)(sm + OVLO + (ldc + 3) * 144 + row * 2) = (uint16_t)(l1 >> 16);
        }
    };

    float cO[8][4];
#pragma unroll
    for (int j = 0; j < 8; ++j)
#pragma unroll
        for (int k = 0; k < 4; ++k) cO[j][k] = 0.f;
    float mrow[2] = {NEG_INF, NEG_INF};
    float lrow[2] = {0.f, 0.f};

    ldkv(0); stkv(); __syncthreads();

    for (int kt = 0; kt < nkt; ++kt) {
        if (kt + 1 < nkt) ldkv(kt + 1);

        // ---- S = Q K^T ----
        float cS[8][4];
#pragma unroll
        for (int j = 0; j < 8; ++j)
#pragma unroll
            for (int k = 0; k < 4; ++k) cS[j][k] = 0.f;

#pragma unroll
        for (int ks = 0; ks < 4; ++ks) {
            const int koff = ks * 32 + t * 4;
            uint32_t qh[4], ql[4];
            const char* p = sm + OQHI + (wid * 16 + g) * 144 + koff;
            const char* q = sm + OQLO + (wid * 16 + g) * 144 + koff;
            qh[0] = *(const uint32_t*)p;          qh[1] = *(const uint32_t*)(p + 1152);
            qh[2] = *(const uint32_t*)(p + 16);   qh[3] = *(const uint32_t*)(p + 1168);
            ql[0] = *(const uint32_t*)q;          ql[1] = *(const uint32_t*)(q + 1152);
            ql[2] = *(const uint32_t*)(q + 16);   ql[3] = *(const uint32_t*)(q + 1168);
#pragma unroll
            for (int nj = 0; nj < 8; ++nj) {
                const char* kp = sm + OKHI + (nj * 8 + g) * 144 + koff;
                const char* kq = sm + OKLO + (nj * 8 + g) * 144 + koff;
                uint32_t kb[2]  = {*(const uint32_t*)kp, *(const uint32_t*)(kp + 16)};
                uint32_t klb[2] = {*(const uint32_t*)kq, *(const uint32_t*)(kq + 16)};
                mma16816(cS[nj], qh, kb);
                mma16816(cS[nj], qh, klb);
                mma16816(cS[nj], ql, kb);
            }
        }

        // ---- online softmax (row halves: h=0 -> row g, h=1 -> row g+8) ----
        const int kb0 = kt * 64;
#pragma unroll
        for (int h = 0; h < 2; ++h) {
            const int qrow = qbase + wid * 16 + g + 8 * h;
            float mloc = NEG_INF;
#pragma unroll
            for (int nj = 0; nj < 8; ++nj)
#pragma unroll
                for (int cc = 0; cc < 2; ++cc) {
                    const int key = kb0 + nj * 8 + 2 * t + cc;
                    float v = cS[nj][2 * h + cc] * SC;
                    if (key > qrow) v = NEG_INF;
                    cS[nj][2 * h + cc] = v;
                    mloc = fmaxf(mloc, v);
                }
            mloc = fmaxf(mloc, __shfl_xor_sync(0xffffffffu, mloc, 1));
            mloc = fmaxf(mloc, __shfl_xor_sync(0xffffffffu, mloc, 2));
            const float mnew  = fmaxf(mrow[h], mloc);
            const float alpha = ex2f(mrow[h] - mnew);
            mrow[h] = mnew;
            float rs = 0.f;
#pragma unroll
            for (int nj = 0; nj < 8; ++nj)
#pragma unroll
                for (int cc = 0; cc < 2; ++cc) {
                    float ppp = ex2f(cS[nj][2 * h + cc] - mnew);
                    cS[nj][2 * h + cc] = ppp;
                    rs += ppp;
                }
            rs += __shfl_xor_sync(0xffffffffu, rs, 1);
            rs += __shfl_xor_sync(0xffffffffu, rs, 2);
            lrow[h] = lrow[h] * alpha + rs;
#pragma unroll
            for (int nj = 0; nj < 8; ++nj) {
                cO[nj][2 * h + 0] *= alpha;
                cO[nj][2 * h + 1] *= alpha;
            }
        }

        // ---- O += P V  (P repacked from cS in registers) ----
#pragma unroll
        for (int ks = 0; ks < 4; ++ks) {
            uint32_t ph[4], pl[4];
            split2(cS[2 * ks][0],     cS[2 * ks][1],     ph[0], pl[0]);
            split2(cS[2 * ks][2],     cS[2 * ks][3],     ph[1], pl[1]);
            split2(cS[2 * ks + 1][0], cS[2 * ks + 1][1], ph[2], pl[2]);
            split2(cS[2 * ks + 1][2], cS[2 * ks + 1][3], ph[3], pl[3]);
            const int koff = ks * 32 + t * 4;
#pragma unroll
            for (int nj = 0; nj < 8; ++nj) {
                const char* vp = sm + OVHI + (nj * 8 + g) * 144 + koff;
                const char* vq = sm + OVLO + (nj * 8 + g) * 144 + koff;
                uint32_t vb[2]  = {*(const uint32_t*)vp, *(const uint32_t*)(vp + 16)};
                uint32_t vlb[2] = {*(const uint32_t*)vq, *(const uint32_t*)(vq + 16)};
                mma16816(cO[nj], ph, vb);
                mma16816(cO[nj], pl, vb);
                mma16816(cO[nj], ph, vlb);
            }
        }

        __syncthreads();
        if (kt + 1 < nkt) { stkv(); __syncthreads(); }
    }

    // ---- epilogue: normalize, write [B,T,D] for proj GEMM ----
    const float i0 = 1.f / lrow[0];
    const float i1 = 1.f / lrow[1];
    const int q0 = qbase + wid * 16 + g;
    const int b  = bh >> 4, hh = bh & 15;
    float* O0 = g_attn + (size_t)(b * T_ + q0) * D_ + hh * 64 + 2 * t;
    float* O1 = O0 + (size_t)8 * D_;
#pragma unroll
    for (int nj = 0; nj < 8; ++nj) {
        *(float2*)(O0 + nj * 8) = make_float2(cO[nj][0] * i0, cO[nj][1] * i0);
        *(float2*)(O1 + nj * 8) = make_float2(cO[nj][2] * i1, cO[nj][3] * i1);
    }
}

// =====================================================================
extern "C" void kernel_launch(void* const* d_in, const int* in_sizes, int n_in,
                              void* d_out, int out_size)
{
    const float* x     = (const float*)d_in[0];
    const float* Wqkv  = (const float*)d_in[1];
    const float* Wproj = (const float*)d_in[2];
    const float* bproj = (const float*)d_in[3];
    float* out = (float*)d_out;
    (void)in_sizes; (void)n_in; (void)out_size;

    cudaFuncSetAttribute(flash_mma, cudaFuncAttributeMaxDynamicSharedMemorySize, FA_SMEM);

    dim3 gq(N_QKV / 128, M1 / 128);   // 24 x 64
    gemm_mma<0><<<gq, 256>>>(x, Wqkv, nullptr, nullptr);

    dim3 ga(T_ / 128, B_ * H_);       // 16 x 64
    flash_mma<<<ga, 256, FA_SMEM>>>();

    dim3 gp(D_ / 128, M1 / 128);      // 8 x 64
    gemm_mma<1><<<gp, 256>>>(nullptr, Wproj, bproj, out);
}

// round 4
// speedup vs baseline: 2.8206x; 1.2042x over previous
#include <cuda_runtime.h>
#include <cuda_fp16.h>
#include <cstdint>

#define DEVINLINE __device__ __forceinline__

constexpr int B_  = 4;
constexpr int T_  = 2048;
constexpr int D_  = 1024;
constexpr int H_  = 16;
constexpr int HD_ = 64;
constexpr int M1  = B_ * T_;      // 8192
constexpr int N_QKV = 3 * D_;     // 3072

// ---- scratch ----
__device__ float g_Q[(size_t)B_ * H_ * T_ * HD_];
__device__ float g_K[(size_t)B_ * H_ * T_ * HD_];
__device__ float g_V[(size_t)B_ * H_ * T_ * HD_];
__device__ float g_attn[(size_t)M1 * D_];

// =====================================================================
// helpers (arch-portable PTX only)
// =====================================================================
DEVINLINE float ex2f(float x) {
    float y; asm("ex2.approx.ftz.f32 %0, %1;" : "=f"(y) : "f"(x)); return y;
}

// pack two floats to fp16x2 (x -> low half, y -> high half)
DEVINLINE uint32_t pack2h(float x, float y) {
    __half2 h = __floats2half2_rn(x, y);
    return *reinterpret_cast<uint32_t*>(&h);
}

// split pair (x,y) into fp16 hi pair + fp16 lo (residual) pair
DEVINLINE void split2h(float x, float y, uint32_t& hi, uint32_t& lo) {
    __half hx = __float2half_rn(x), hy = __float2half_rn(y);
    hi = ((uint32_t)__half_as_ushort(hy) << 16) | (uint32_t)__half_as_ushort(hx);
    float rx = x - __half2float(hx);
    float ry = y - __half2float(hy);
    lo = pack2h(rx, ry);
}

DEVINLINE void mma16816(float c[4], const uint32_t a[4], const uint32_t b[2]) {
    asm volatile(
        "mma.sync.aligned.m16n8k16.row.col.f32.f16.f16.f32 "
        "{%0,%1,%2,%3}, {%4,%5,%6,%7}, {%8,%9}, {%0,%1,%2,%3};"
        : "+f"(c[0]), "+f"(c[1]), "+f"(c[2]), "+f"(c[3])
        : "r"(a[0]), "r"(a[1]), "r"(a[2]), "r"(a[3]), "r"(b[0]), "r"(b[1]));
}

// =====================================================================
// HMMA GEMM, fp16 2-term: C = (Ah+Al)*Wh.  Tile 128x128x16, 4 warps
// (2x2 grid, warp tile 64x64).  Row stride 48B: frag banks 12g+t -> all 32.
// MODE 0: A=x, scatter into g_Q/g_K/g_V.   MODE 1: A=g_attn, out+bias.
// =====================================================================
constexpr int GRS   = 48;                // smem row stride bytes (16 halves + pad)
constexpr int GTILE = 128 * GRS;         // 6144 B per (hi|lo) tile

template <int MODE>
__global__ __launch_bounds__(128, 2)
void gemm_mma(const float* __restrict__ Ain, const float* __restrict__ W,
              const float* __restrict__ bias, float* __restrict__ Cout)
{
    __shared__ __align__(16) char smA[2][2 * GTILE];   // [stage][Ahi|Alo]
    __shared__ __align__(16) char smB[2][GTILE];       // [stage][Bhi]
    const float* A = (MODE == 1) ? (const float*)g_attn : Ain;

    const int tid = threadIdx.x, lane = tid & 31, wid = tid >> 5;
    const int g = lane >> 2, t = lane & 3;
    const int wm = wid >> 1, wn = wid & 1;
    const int bm = blockIdx.y * 128, bn = blockIdx.x * 128;

    const int ldr = tid >> 2;            // 0..31
    const int ldc = (tid & 3) << 2;      // 0,4,8,12

    float c[4][8][4];
#pragma unroll
    for (int i = 0; i < 4; ++i)
#pragma unroll
        for (int j = 0; j < 8; ++j)
#pragma unroll
            for (int k = 0; k < 4; ++k) c[i][j][k] = 0.f;

    float4 ra[4], rb[4];
    auto ldg = [&](int k0) {
#pragma unroll
        for (int u = 0; u < 4; ++u) {
            ra[u] = *(const float4*)(A + (size_t)(bm + ldr + 32 * u) * D_ + k0 + ldc);
            rb[u] = *(const float4*)(W + (size_t)(bn + ldr + 32 * u) * D_ + k0 + ldc);
        }
    };
    auto sts = [&](int st) {
#pragma unroll
        for (int u = 0; u < 4; ++u) {
            const int row = ldr + 32 * u;
            uint32_t h0, l0, h1, l1;
            split2h(ra[u].x, ra[u].y, h0, l0);
            split2h(ra[u].z, ra[u].w, h1, l1);
            *(uint2*)(smA[st] + row * GRS + ldc * 2) = make_uint2(h0, h1);
            *(uint2*)(smA[st] + GTILE + row * GRS + ldc * 2) = make_uint2(l0, l1);
            *(uint2*)(smB[st] + row * GRS + ldc * 2) =
                make_uint2(pack2h(rb[u].x, rb[u].y), pack2h(rb[u].z, rb[u].w));
        }
    };

    ldg(0); sts(0); __syncthreads();

    constexpr int NT = D_ / 16;          // 64 stages
    for (int kt = 0; kt < NT; ++kt) {
        const int st = kt & 1;
        if (kt + 1 < NT) ldg((kt + 1) * 16);

        const int koff = t * 4;
        uint32_t ah[4][4], al[4][4];
#pragma unroll
        for (int mi = 0; mi < 4; ++mi) {
            const char* p = smA[st] + (wm * 64 + mi * 16 + g) * GRS + koff;
            const char* q = p + GTILE;
            ah[mi][0] = *(const uint32_t*)p;
            ah[mi][1] = *(const uint32_t*)(p + 8 * GRS);
            ah[mi][2] = *(const uint32_t*)(p + 16);
            ah[mi][3] = *(const uint32_t*)(p + 8 * GRS + 16);
            al[mi][0] = *(const uint32_t*)q;
            al[mi][1] = *(const uint32_t*)(q + 8 * GRS);
            al[mi][2] = *(const uint32_t*)(q + 16);
            al[mi][3] = *(const uint32_t*)(q + 8 * GRS + 16);
        }
#pragma unroll
        for (int nj = 0; nj < 8; ++nj) {
            const char* p = smB[st] + (wn * 64 + nj * 8 + g) * GRS + koff;
            uint32_t bh[2] = {*(const uint32_t*)p, *(const uint32_t*)(p + 16)};
#pragma unroll
            for (int mi = 0; mi < 4; ++mi) {
                mma16816(c[mi][nj], ah[mi], bh);
                mma16816(c[mi][nj], al[mi], bh);
            }
        }
        __syncthreads();
        if (kt + 1 < NT) { sts(st ^ 1); __syncthreads(); }
    }

    // epilogue
#pragma unroll
    for (int mi = 0; mi < 4; ++mi) {
        const int r0 = bm + wm * 64 + mi * 16 + g;
        const int r1 = r0 + 8;
#pragma unroll
        for (int nj = 0; nj < 8; ++nj) {
            const int cn = bn + wn * 64 + nj * 8 + 2 * t;
            if (MODE == 0) {
                const int part = cn >> 10, ccc = cn & 1023;
                const int hh = ccc >> 6, dd = ccc & 63;
                float* dst = (part == 0) ? g_Q : (part == 1) ? g_K : g_V;
                {
                    const int bb = r0 >> 11, tt = r0 & 2047;
                    *(float2*)&dst[(((size_t)(bb * H_ + hh) * T_ + tt) << 6) + dd] =
                        make_float2(c[mi][nj][0], c[mi][nj][1]);
                }
                {
                    const int bb = r1 >> 11, tt = r1 & 2047;
                    *(float2*)&dst[(((size_t)(bb * H_ + hh) * T_ + tt) << 6) + dd] =
                        make_float2(c[mi][nj][2], c[mi][nj][3]);
                }
            } else {
                float2 bv = *(const float2*)&bias[cn];
                *(float2*)&Cout[(size_t)r0 * D_ + cn] =
                    make_float2(c[mi][nj][0] + bv.x, c[mi][nj][1] + bv.y);
                *(float2*)&Cout[(size_t)r1 * D_ + cn] =
                    make_float2(c[mi][nj][2] + bv.x, c[mi][nj][3] + bv.y);
            }
        }
    }
}

// =====================================================================
// HMMA flash attention, causal, fp16 3-term, Q frags hoisted to regs.
// q-tile 128 (warp w: rows w*16..+15), k-tile 64, hd 64.
// =====================================================================
constexpr int ARS  = 72;               // half row stride (64 -> 72): conflict-free
constexpr int AQB  = 128 * ARS * 2;    // 18432
constexpr int AKB  = 64 * ARS * 2;     // 9216
constexpr int OQHI = 0, OQLO = AQB;
constexpr int OKHI = 2 * AQB, OKLO = OKHI + AKB;
constexpr int OVHI = OKLO + AKB, OVLO = OVHI + AKB;
constexpr int FA_SMEM = OVLO + AKB;    // 73728

__global__ __launch_bounds__(256, 1)
void flash_mma()
{
    extern __shared__ __align__(16) char sm[];
    const int tid = threadIdx.x, lane = tid & 31, wid = tid >> 5;
    const int g = lane >> 2, t = lane & 3;
    const int qt = blockIdx.x, bh = blockIdx.y;
    const int qbase = qt * 128;
    const int nkt = 2 * qt + 2;

    const float* Qg = g_Q + (size_t)bh * T_ * HD_;
    const float* Kg = g_K + (size_t)bh * T_ * HD_;
    const float* Vg = g_V + (size_t)bh * T_ * HD_;

    const float NEG_INF = __int_as_float(0xff800000);
    const float SC = 0.18033688011112042385f;   // log2(e)/sqrt(64)

    const int ldrq = tid >> 4;         // 0..15
    const int ldc  = (tid & 15) * 4;   // 0..60

    // ---- stage Q tile (hi/lo split) ----
#pragma unroll
    for (int u = 0; u < 8; ++u) {
        const int row = ldrq + 16 * u;
        float4 v = *(const float4*)(Qg + (size_t)(qbase + row) * HD_ + ldc);
        uint32_t h0, l0, h1, l1;
        split2h(v.x, v.y, h0, l0);
        split2h(v.z, v.w, h1, l1);
        *(uint2*)(sm + OQHI + row * 144 + ldc * 2) = make_uint2(h0, h1);
        *(uint2*)(sm + OQLO + row * 144 + ldc * 2) = make_uint2(l0, l1);
    }

    float4 rk[4], rv[4];
    auto ldkv = [&](int kt) {
#pragma unroll
        for (int u = 0; u < 4; ++u) {
            const int row = ldrq + 16 * u;
            rk[u] = *(const float4*)(Kg + (size_t)(kt * 64 + row) * HD_ + ldc);
            rv[u] = *(const float4*)(Vg + (size_t)(kt * 64 + row) * HD_ + ldc);
        }
    };
    auto stkv = [&]() {
#pragma unroll
        for (int u = 0; u < 4; ++u) {
            const int row = ldrq + 16 * u;
            uint32_t h0, l0, h1, l1;
            split2h(rk[u].x, rk[u].y, h0, l0);
            split2h(rk[u].z, rk[u].w, h1, l1);
            *(uint2*)(sm + OKHI + row * 144 + ldc * 2) = make_uint2(h0, h1);
            *(uint2*)(sm + OKLO + row * 144 + ldc * 2) = make_uint2(l0, l1);
            // V transposed: Vt[hd][key]
            split2h(rv[u].x, rv[u].y, h0, l0);
            split2h(rv[u].z, rv[u].w, h1, l1);
            *(uint16_t*)(sm + OVHI + (ldc + 0) * 144 + row * 2) = (uint16_t)(h0 & 0xffff);
            *(uint16_t*)(sm + OVHI + (ldc + 1) * 144 + row * 2) = (uint16_t)(h0 >> 16);
            *(uint16_t*)(sm + OVHI + (ldc + 2) * 144 + row * 2) = (uint16_t)(h1 & 0xffff);
            *(uint16_t*)(sm + OVHI + (ldc + 3) * 144 + row * 2) = (uint16_t)(h1 >> 16);
            *(uint16_t*)(sm + OVLO + (ldc + 0) * 144 + row * 2) = (uint16_t)(l0 & 0xffff);
            *(uint16_t*)(sm + OVLO + (ldc + 1) * 144 + row * 2) = (uint16_t)(l0 >> 16);
            *(uint16_t*)(sm + OVLO + (ldc + 2) * 144 + row * 2) = (uint16_t)(l1 & 0xffff);
            *(uint16_t*)(sm + OVLO + (ldc + 3) * 144 + row * 2) = (uint16_t)(l1 >> 16);
        }
    };

    float cO[8][4];
#pragma unroll
    for (int j = 0; j < 8; ++j)
#pragma unroll
        for (int k = 0; k < 4; ++k) cO[j][k] = 0.f;
    float mrow[2] = {NEG_INF, NEG_INF};
    float lrow[2] = {0.f, 0.f};

    ldkv(0); stkv(); __syncthreads();

    // ---- hoist Q fragments (loop-invariant) ----
    uint32_t qh[4][4], ql[4][4];
#pragma unroll
    for (int ks = 0; ks < 4; ++ks) {
        const int koff = ks * 32 + t * 4;
        const char* p = sm + OQHI + (wid * 16 + g) * 144 + koff;
        const char* q = sm + OQLO + (wid * 16 + g) * 144 + koff;
        qh[ks][0] = *(const uint32_t*)p;        qh[ks][1] = *(const uint32_t*)(p + 1152);
        qh[ks][2] = *(const uint32_t*)(p + 16); qh[ks][3] = *(const uint32_t*)(p + 1168);
        ql[ks][0] = *(const uint32_t*)q;        ql[ks][1] = *(const uint32_t*)(q + 1152);
        ql[ks][2] = *(const uint32_t*)(q + 16); ql[ks][3] = *(const uint32_t*)(q + 1168);
    }

    for (int kt = 0; kt < nkt; ++kt) {
        if (kt + 1 < nkt) ldkv(kt + 1);

        // ---- S = Q K^T  (3-term) ----
        float cS[8][4];
#pragma unroll
        for (int j = 0; j < 8; ++j)
#pragma unroll
            for (int k = 0; k < 4; ++k) cS[j][k] = 0.f;

#pragma unroll
        for (int ks = 0; ks < 4; ++ks) {
            const int koff = ks * 32 + t * 4;
#pragma unroll
            for (int nj = 0; nj < 8; ++nj) {
                const char* kp = sm + OKHI + (nj * 8 + g) * 144 + koff;
                const char* kq = sm + OKLO + (nj * 8 + g) * 144 + koff;
                uint32_t kb[2]  = {*(const uint32_t*)kp, *(const uint32_t*)(kp + 16)};
                uint32_t klb[2] = {*(const uint32_t*)kq, *(const uint32_t*)(kq + 16)};
                mma16816(cS[nj], qh[ks], kb);
                mma16816(cS[nj], qh[ks], klb);
                mma16816(cS[nj], ql[ks], kb);
            }
        }

        // ---- online softmax ----
        const int kb0 = kt * 64;
#pragma unroll
        for (int h = 0; h < 2; ++h) {
            const int qrow = qbase + wid * 16 + g + 8 * h;
            float mloc = NEG_INF;
#pragma unroll
            for (int nj = 0; nj < 8; ++nj)
#pragma unroll
                for (int cc = 0; cc < 2; ++cc) {
                    const int key = kb0 + nj * 8 + 2 * t + cc;
                    float v = cS[nj][2 * h + cc] * SC;
                    if (key > qrow) v = NEG_INF;
                    cS[nj][2 * h + cc] = v;
                    mloc = fmaxf(mloc, v);
                }
            mloc = fmaxf(mloc, __shfl_xor_sync(0xffffffffu, mloc, 1));
            mloc = fmaxf(mloc, __shfl_xor_sync(0xffffffffu, mloc, 2));
            const float mnew  = fmaxf(mrow[h], mloc);
            const float alpha = ex2f(mrow[h] - mnew);
            mrow[h] = mnew;
            float rs = 0.f;
#pragma unroll
            for (int nj = 0; nj < 8; ++nj)
#pragma unroll
                for (int cc = 0; cc < 2; ++cc) {
                    float ppp = ex2f(cS[nj][2 * h + cc] - mnew);
                    cS[nj][2 * h + cc] = ppp;
                    rs += ppp;
                }
            rs += __shfl_xor_sync(0xffffffffu, rs, 1);
            rs += __shfl_xor_sync(0xffffffffu, rs, 2);
            lrow[h] = lrow[h] * alpha + rs;
#pragma unroll
            for (int nj = 0; nj < 8; ++nj) {
                cO[nj][2 * h + 0] *= alpha;
                cO[nj][2 * h + 1] *= alpha;
            }
        }

        // ---- O += P V  (3-term, P split in registers) ----
#pragma unroll
        for (int ks = 0; ks < 4; ++ks) {
            uint32_t ph[4], pl[4];
            split2h(cS[2 * ks][0],     cS[2 * ks][1],     ph[0], pl[0]);
            split2h(cS[2 * ks][2],     cS[2 * ks][3],     ph[1], pl[1]);
            split2h(cS[2 * ks + 1][0], cS[2 * ks + 1][1], ph[2], pl[2]);
            split2h(cS[2 * ks + 1][2], cS[2 * ks + 1][3], ph[3], pl[3]);
            const int koff = ks * 32 + t * 4;
#pragma unroll
            for (int nj = 0; nj < 8; ++nj) {
                const char* vp = sm + OVHI + (nj * 8 + g) * 144 + koff;
                const char* vq = sm + OVLO + (nj * 8 + g) * 144 + koff;
                uint32_t vb[2]  = {*(const uint32_t*)vp, *(const uint32_t*)(vp + 16)};
                uint32_t vlb[2] = {*(const uint32_t*)vq, *(const uint32_t*)(vq + 16)};
                mma16816(cO[nj], ph, vb);
                mma16816(cO[nj], pl, vb);
                mma16816(cO[nj], ph, vlb);
            }
        }

        __syncthreads();
        if (kt + 1 < nkt) { stkv(); __syncthreads(); }
    }

    // ---- epilogue ----
    const float i0 = 1.f / lrow[0];
    const float i1 = 1.f / lrow[1];
    const int q0 = qbase + wid * 16 + g;
    const int b  = bh >> 4, hh = bh & 15;
    float* O0 = g_attn + (size_t)(b * T_ + q0) * D_ + hh * 64 + 2 * t;
    float* O1 = O0 + (size_t)8 * D_;
#pragma unroll
    for (int nj = 0; nj < 8; ++nj) {
        *(float2*)(O0 + nj * 8) = make_float2(cO[nj][0] * i0, cO[nj][1] * i0);
        *(float2*)(O1 + nj * 8) = make_float2(cO[nj][2] * i1, cO[nj][3] * i1);
    }
}

// =====================================================================
extern "C" void kernel_launch(void* const* d_in, const int* in_sizes, int n_in,
                              void* d_out, int out_size)
{
    const float* x     = (const float*)d_in[0];
    const float* Wqkv  = (const float*)d_in[1];
    const float* Wproj = (const float*)d_in[2];
    const float* bproj = (const float*)d_in[3];
    float* out = (float*)d_out;
    (void)in_sizes; (void)n_in; (void)out_size;

    cudaFuncSetAttribute(flash_mma, cudaFuncAttributeMaxDynamicSharedMemorySize, FA_SMEM);

    dim3 gq(N_QKV / 128, M1 / 128);   // 24 x 64
    gemm_mma<0><<<gq, 128>>>(x, Wqkv, nullptr, nullptr);

    dim3 ga(T_ / 128, B_ * H_);       // 16 x 64
    flash_mma<<<ga, 256, FA_SMEM>>>();

    dim3 gp(D_ / 128, M1 / 128);      // 8 x 64
    gemm_mma<1><<<gp, 128>>>(nullptr, Wproj, bproj, out);
}

// round 6
// speedup vs baseline: 3.3215x; 1.1776x over previous
#include <cuda_runtime.h>
#include <cuda_fp16.h>
#include <cstdint>

#define DEVINLINE __device__ __forceinline__

constexpr int B_  = 4;
constexpr int T_  = 2048;
constexpr int D_  = 1024;
constexpr int H_  = 16;
constexpr int HD_ = 64;
constexpr int M1  = B_ * T_;              // 8192
constexpr int N_QKV = 3 * D_;             // 3072
constexpr size_t NE = (size_t)M1 * D_;    // 8388608

// ---- scratch (static __device__; no allocation allowed) ----
__device__ __half g_xh[NE], g_xl[NE];
__device__ __half g_wqh[(size_t)N_QKV * D_];
__device__ __half g_wph[(size_t)D_ * D_];
__device__ __half g_Qh[NE], g_Ql[NE], g_Kh[NE], g_Kl[NE];
__device__ float  g_Vf[NE];
__device__ __half g_Vth[NE], g_Vtl[NE];
__device__ __half g_Oh[NE], g_Ol[NE];

// =====================================================================
// helpers (arch-portable PTX only: mma.sync/ldmatrix/cp.async)
// =====================================================================
DEVINLINE uint32_t smem_u32(const void* p) {
    uint32_t a;
    asm("{ .reg .u64 t; cvta.to.shared.u64 t, %1; cvt.u32.u64 %0, t; }" : "=r"(a) : "l"(p));
    return a;
}
DEVINLINE float ex2f(float x) {
    float y; asm("ex2.approx.ftz.f32 %0, %1;" : "=f"(y) : "f"(x)); return y;
}
DEVINLINE uint32_t pack2h(float x, float y) {
    __half2 h = __floats2half2_rn(x, y);
    return *reinterpret_cast<uint32_t*>(&h);
}
DEVINLINE void split2h(float x, float y, uint32_t& hi, uint32_t& lo) {
    __half hx = __float2half_rn(x), hy = __float2half_rn(y);
    hi = ((uint32_t)__half_as_ushort(hy) << 16) | (uint32_t)__half_as_ushort(hx);
    lo = pack2h(x - __half2float(hx), y - __half2float(hy));
}
DEVINLINE void mma16816(float c[4], const uint32_t a[4], const uint32_t b[2]) {
    asm volatile(
        "mma.sync.aligned.m16n8k16.row.col.f32.f16.f16.f32 "
        "{%0,%1,%2,%3}, {%4,%5,%6,%7}, {%8,%9}, {%0,%1,%2,%3};"
        : "+f"(c[0]), "+f"(c[1]), "+f"(c[2]), "+f"(c[3])
        : "r"(a[0]), "r"(a[1]), "r"(a[2]), "r"(a[3]), "r"(b[0]), "r"(b[1]));
}
#define LDSM4(r0, r1, r2, r3, addr)                                           \
    asm volatile("ldmatrix.sync.aligned.m8n8.x4.shared.b16 {%0,%1,%2,%3}, [%4];" \
        : "=r"(r0), "=r"(r1), "=r"(r2), "=r"(r3) : "r"(addr))
DEVINLINE void ldsm4a(uint32_t r[4], uint32_t addr) { LDSM4(r[0], r[1], r[2], r[3], addr); }
DEVINLINE void cp16(uint32_t dst, const void* src) {
    asm volatile("cp.async.cg.shared.global [%0], [%1], 16;" :: "r"(dst), "l"(src));
}
#define CP_COMMIT() asm volatile("cp.async.commit_group;" ::: "memory")
#define CP_WAIT0()  asm volatile("cp.async.wait_group 0;" ::: "memory")
#define CP_WAIT2()  asm volatile("cp.async.wait_group 2;" ::: "memory")

// =====================================================================
// convert inputs: x -> (hi,lo) fp16; W_qkv, W_proj -> hi fp16
// =====================================================================
constexpr size_t CX = NE / 4;                          // 2097152 float4
constexpr size_t CQ = (size_t)N_QKV * D_ / 4;          // 786432
constexpr size_t CP = (size_t)D_ * D_ / 4;             // 262144
__global__ void convert_in(const float* __restrict__ x, const float* __restrict__ wq,
                           const float* __restrict__ wp)
{
    size_t i = (size_t)blockIdx.x * 256 + threadIdx.x;
    if (i < CX) {
        float4 v = ((const float4*)x)[i];
        uint32_t h0, l0, h1, l1;
        split2h(v.x, v.y, h0, l0);
        split2h(v.z, v.w, h1, l1);
        ((uint2*)g_xh)[i] = make_uint2(h0, h1);
        ((uint2*)g_xl)[i] = make_uint2(l0, l1);
    } else if (i < CX + CQ) {
        size_t j = i - CX;
        float4 v = ((const float4*)wq)[j];
        ((uint2*)g_wqh)[j] = make_uint2(pack2h(v.x, v.y), pack2h(v.z, v.w));
    } else {
        size_t j = i - CX - CQ;
        float4 v = ((const float4*)wp)[j];
        ((uint2*)g_wph)[j] = make_uint2(pack2h(v.x, v.y), pack2h(v.z, v.w));
    }
}

// =====================================================================
// transpose V: g_Vf [bh][t][d] fp32 -> g_Vth/g_Vtl [bh][d][t] fp16
// =====================================================================
__global__ void transpose_v()
{
    __shared__ float ts[64][65];
    const int bh = blockIdx.y, tt = blockIdx.x, tid = threadIdx.x;
    const float* src = g_Vf + (size_t)bh * T_ * HD_ + (size_t)tt * 64 * HD_;
#pragma unroll
    for (int u = 0; u < 4; ++u) {
        int idx = tid + 256 * u;            // 1024 float4
        int r = idx >> 4, c4 = (idx & 15) * 4;
        float4 v = *(const float4*)(src + r * HD_ + c4);
        ts[r][c4] = v.x; ts[r][c4 + 1] = v.y; ts[r][c4 + 2] = v.z; ts[r][c4 + 3] = v.w;
    }
    __syncthreads();
#pragma unroll
    for (int u = 0; u < 8; ++u) {
        int idx = tid + 256 * u;            // 2048 pairs
        int d = idx >> 5, tp = (idx & 31) * 2;
        uint32_t hi, lo;
        split2h(ts[tp][d], ts[tp + 1][d], hi, lo);
        size_t o = (size_t)bh * T_ * HD_ + (size_t)d * T_ + tt * 64 + tp;
        *(uint32_t*)(g_Vth + o) = hi;
        *(uint32_t*)(g_Vtl + o) = lo;
    }
}

// =====================================================================
// HMMA GEMM (fp16 2-term, preconverted operands, cp.async 4-stage,
// ldmatrix fragments). Tile 128x128x16, 8 warps (4m x 2n).
// MODE 0: scatter Qh/Ql/Kh/Kl + Vf.   MODE 1: out = A*W^T + bias.
// =====================================================================
constexpr int STG_B = 18432;     // Ah(6144) + Al(6144) + Bh(6144), rows 48B
constexpr int G_SMEM = 4 * STG_B;

template <int MODE>
__global__ __launch_bounds__(256, 2)
void gemm_mma(const float* __restrict__ bias, float* __restrict__ Cout)
{
    extern __shared__ __align__(16) char smg[];
    const uint32_t sb = smem_u32(smg);
    const __half* Ah = (MODE == 0) ? g_xh : g_Oh;
    const __half* Al = (MODE == 0) ? g_xl : g_Ol;
    const __half* Bh = (MODE == 0) ? g_wqh : g_wph;

    const int tid = threadIdx.x, lane = tid & 31, wid = tid >> 5;
    const int g = lane >> 2, t = lane & 3;
    const int wm = wid >> 1, wn = wid & 1;
    const int bm = blockIdx.y * 128, bn = blockIdx.x * 128;

    float c[2][8][4];
#pragma unroll
    for (int i = 0; i < 2; ++i)
#pragma unroll
        for (int j = 0; j < 8; ++j)
#pragma unroll
            for (int k = 0; k < 4; ++k) c[i][j][k] = 0.f;

    const int ldrow = tid >> 1, ldh = (tid & 1) * 8;
    auto issue = [&](int s, int kt) {
        const uint32_t dst = sb + s * STG_B + ldrow * 48 + ldh * 2;
        const int k0 = kt * 16 + ldh;
        cp16(dst,         Ah + (size_t)(bm + ldrow) * D_ + k0);
        cp16(dst + 6144,  Al + (size_t)(bm + ldrow) * D_ + k0);
        cp16(dst + 12288, Bh + (size_t)(bn + ldrow) * D_ + k0);
    };

    const uint32_t aoff = (uint32_t)((wm * 32 + (lane & 7) + (lane & 8)) * 48 + (lane >> 4) * 16);
    const uint32_t boff = (uint32_t)(12288 + (wn * 64 + (lane & 7) + ((lane >> 1) & 8)) * 48 + (lane & 8) * 2);

#pragma unroll 1
    for (int s = 0; s < 3; ++s) { issue(s, s); CP_COMMIT(); }

    constexpr int NT = D_ / 16;   // 64
    for (int kt = 0; kt < NT; ++kt) {
        CP_WAIT2();
        __syncthreads();
        if (kt + 3 < NT) issue((kt + 3) & 3, kt + 3);
        CP_COMMIT();

        const uint32_t stb = sb + (kt & 3) * STG_B;
        uint32_t ah[2][4], al[2][4];
        ldsm4a(ah[0], stb + aoff);
        ldsm4a(ah[1], stb + aoff + 768);
        ldsm4a(al[0], stb + aoff + 6144);
        ldsm4a(al[1], stb + aoff + 6912);
#pragma unroll
        for (int njp = 0; njp < 4; ++njp) {
            uint32_t b0, b1, b2, b3;
            LDSM4(b0, b1, b2, b3, stb + boff + njp * 768);
            uint32_t bA[2] = {b0, b1}, bB[2] = {b2, b3};
            mma16816(c[0][2 * njp], ah[0], bA);
            mma16816(c[0][2 * njp], al[0], bA);
            mma16816(c[1][2 * njp], ah[1], bA);
            mma16816(c[1][2 * njp], al[1], bA);
            mma16816(c[0][2 * njp + 1], ah[0], bB);
            mma16816(c[0][2 * njp + 1], al[0], bB);
            mma16816(c[1][2 * njp + 1], ah[1], bB);
            mma16816(c[1][2 * njp + 1], al[1], bB);
        }
    }

    // epilogue
#pragma unroll
    for (int mi = 0; mi < 2; ++mi) {
        const int r0 = bm + wm * 32 + mi * 16 + g;
        const int r1 = r0 + 8;
#pragma unroll
        for (int nj = 0; nj < 8; ++nj) {
            const int cn = bn + wn * 64 + nj * 8 + 2 * t;
            if (MODE == 0) {
                const int part = cn >> 10, hh = (cn >> 6) & 15, dd = cn & 63;
                const int bb0 = r0 >> 11, tt0 = r0 & 2047;
                const int bb1 = r1 >> 11, tt1 = r1 & 2047;
                const size_t o0 = (((size_t)(bb0 * H_ + hh) * T_ + tt0) << 6) + dd;
                const size_t o1 = (((size_t)(bb1 * H_ + hh) * T_ + tt1) << 6) + dd;
                if (part == 2) {
                    *(float2*)&g_Vf[o0] = make_float2(c[mi][nj][0], c[mi][nj][1]);
                    *(float2*)&g_Vf[o1] = make_float2(c[mi][nj][2], c[mi][nj][3]);
                } else {
                    __half* dh = (part == 0) ? g_Qh : g_Kh;
                    __half* dl = (part == 0) ? g_Ql : g_Kl;
                    uint32_t hi, lo;
                    split2h(c[mi][nj][0], c[mi][nj][1], hi, lo);
                    *(uint32_t*)(dh + o0) = hi; *(uint32_t*)(dl + o0) = lo;
                    split2h(c[mi][nj][2], c[mi][nj][3], hi, lo);
                    *(uint32_t*)(dh + o1) = hi; *(uint32_t*)(dl + o1) = lo;
                }
            } else {
                float2 bv = *(const float2*)&bias[cn];
                *(float2*)&Cout[(size_t)r0 * D_ + cn] =
                    make_float2(c[mi][nj][0] + bv.x, c[mi][nj][1] + bv.y);
                *(float2*)&Cout[(size_t)r1 * D_ + cn] =
                    make_float2(c[mi][nj][2] + bv.x, c[mi][nj][3] + bv.y);
            }
        }
    }
}

// =====================================================================
// HMMA flash attention, causal, fp16 3-term, all operands preconverted.
// q-tile 128 (warp w: rows w*16..+15), k-tile 64, hd 64.
// smem: 2 KV stages of [Kh|Kl|Vth|Vtl], each 64 rows x 144B.
// =====================================================================
constexpr int KSTG = 4 * 64 * 144;        // 36864
constexpr int FA_SMEM = 2 * KSTG;         // 73728

__global__ __launch_bounds__(256, 1)
void flash_mma()
{
    extern __shared__ __align__(16) char sma[];
    const uint32_t sb = smem_u32(sma);
    const int tid = threadIdx.x, lane = tid & 31, wid = tid >> 5;
    const int g = lane >> 2, t = lane & 3;
    const int qt = blockIdx.x, bh = blockIdx.y;
    const int qbase = qt * 128;
    const int nkt = 2 * qt + 2;

    const size_t hb = (size_t)bh * T_ * HD_;
    const __half* Qhp = g_Qh + hb; const __half* Qlp = g_Ql + hb;
    const __half* Khp = g_Kh + hb; const __half* Klp = g_Kl + hb;
    const __half* Vhp = g_Vth + hb; const __half* Vlp = g_Vtl + hb;

    const float NEG_INF = __int_as_float(0xff800000);
    const float SC = 0.18033688011112042385f;   // log2(e)/sqrt(64)

    // ---- stage Q (hi at sb+0, lo at sb+18432), then hoist fragments ----
#pragma unroll
    for (int u = 0; u < 8; ++u) {
        int cidx = u * 256 + tid;
        int arr = cidx >> 10, row = (cidx >> 3) & 127, ch = cidx & 7;
        const __half* src = (arr ? Qlp : Qhp) + (size_t)(qbase + row) * HD_ + ch * 8;
        cp16(sb + arr * 18432 + row * 144 + ch * 16, src);
    }
    CP_COMMIT(); CP_WAIT0(); __syncthreads();

    uint32_t qh[4][4], ql[4][4];
    {
        const uint32_t qb = sb + (wid * 16 + (lane & 7) + (lane & 8)) * 144 + (lane >> 4) * 16;
#pragma unroll
        for (int ks = 0; ks < 4; ++ks) {
            ldsm4a(qh[ks], qb + ks * 32);
            ldsm4a(ql[ks], qb + 18432 + ks * 32);
        }
    }
    __syncthreads();

    auto issueKV = [&](int s, int kt) {
        const int ktb = kt * 64;
#pragma unroll
        for (int u = 0; u < 8; ++u) {
            int cidx = u * 256 + tid;
            int arr = cidx >> 9, row = (cidx >> 3) & 63, ch = cidx & 7;
            uint32_t dst = sb + s * KSTG + arr * 9216 + row * 144 + ch * 16;
            const __half* src;
            if (arr == 0)      src = Khp + (size_t)(ktb + row) * HD_ + ch * 8;
            else if (arr == 1) src = Klp + (size_t)(ktb + row) * HD_ + ch * 8;
            else if (arr == 2) src = Vhp + (size_t)row * T_ + ktb + ch * 8;
            else               src = Vlp + (size_t)row * T_ + ktb + ch * 8;
            cp16(dst, src);
        }
    };

    float cO[8][4];
#pragma unroll
    for (int j = 0; j < 8; ++j)
#pragma unroll
        for (int k = 0; k < 4; ++k) cO[j][k] = 0.f;
    float mrow[2] = {NEG_INF, NEG_INF};
    float lrow[2] = {0.f, 0.f};

    issueKV(0, 0); CP_COMMIT();

    const uint32_t frow = (uint32_t)(((lane & 7) + ((lane >> 1) & 8)) * 144 + (lane & 8) * 2);

    for (int kt = 0; kt < nkt; ++kt) {
        CP_WAIT0();
        __syncthreads();
        if (kt + 1 < nkt) issueKV((kt + 1) & 1, kt + 1);
        CP_COMMIT();

        const uint32_t stb = sb + (kt & 1) * KSTG;

        // ---- S = Q K^T (3-term) ----
        float cS[8][4];
#pragma unroll
        for (int j = 0; j < 8; ++j)
#pragma unroll
            for (int k = 0; k < 4; ++k) cS[j][k] = 0.f;

        const uint32_t kb = stb + frow;
#pragma unroll
        for (int ks = 0; ks < 4; ++ks) {
#pragma unroll
            for (int njp = 0; njp < 4; ++njp) {
                uint32_t b0, b1, b2, b3, l0, l1, l2, l3;
                LDSM4(b0, b1, b2, b3, kb + njp * 2304 + ks * 32);
                LDSM4(l0, l1, l2, l3, kb + 9216 + njp * 2304 + ks * 32);
                uint32_t bA[2] = {b0, b1}, bB[2] = {b2, b3};
                uint32_t lA[2] = {l0, l1}, lB[2] = {l2, l3};
                mma16816(cS[2 * njp], qh[ks], bA);
                mma16816(cS[2 * njp], qh[ks], lA);
                mma16816(cS[2 * njp], ql[ks], bA);
                mma16816(cS[2 * njp + 1], qh[ks], bB);
                mma16816(cS[2 * njp + 1], qh[ks], lB);
                mma16816(cS[2 * njp + 1], ql[ks], bB);
            }
        }

        // ---- online softmax ----
        const int kb0 = kt * 64;
#pragma unroll
        for (int h = 0; h < 2; ++h) {
            const int qrow = qbase + wid * 16 + g + 8 * h;
            float mloc = NEG_INF;
#pragma unroll
            for (int nj = 0; nj < 8; ++nj)
#pragma unroll
                for (int cc = 0; cc < 2; ++cc) {
                    const int key = kb0 + nj * 8 + 2 * t + cc;
                    float v = cS[nj][2 * h + cc] * SC;
                    if (key > qrow) v = NEG_INF;
                    cS[nj][2 * h + cc] = v;
                    mloc = fmaxf(mloc, v);
                }
            mloc = fmaxf(mloc, __shfl_xor_sync(0xffffffffu, mloc, 1));
            mloc = fmaxf(mloc, __shfl_xor_sync(0xffffffffu, mloc, 2));
            const float mnew  = fmaxf(mrow[h], mloc);
            const float alpha = ex2f(mrow[h] - mnew);
            mrow[h] = mnew;
            float rs = 0.f;
#pragma unroll
            for (int nj = 0; nj < 8; ++nj)
#pragma unroll
                for (int cc = 0; cc < 2; ++cc) {
                    float p = ex2f(cS[nj][2 * h + cc] - mnew);
                    cS[nj][2 * h + cc] = p;
                    rs += p;
                }
            rs += __shfl_xor_sync(0xffffffffu, rs, 1);
            rs += __shfl_xor_sync(0xffffffffu, rs, 2);
            lrow[h] = lrow[h] * alpha + rs;
#pragma unroll
            for (int nj = 0; nj < 8; ++nj) {
                cO[nj][2 * h + 0] *= alpha;
                cO[nj][2 * h + 1] *= alpha;
            }
        }

        // ---- O += P V (3-term; P split in registers) ----
        const uint32_t vb = stb + 18432 + frow;
#pragma unroll
        for (int ks = 0; ks < 4; ++ks) {
            uint32_t ph[4], pl[4];
            split2h(cS[2 * ks][0],     cS[2 * ks][1],     ph[0], pl[0]);
            split2h(cS[2 * ks][2],     cS[2 * ks][3],     ph[1], pl[1]);
            split2h(cS[2 * ks + 1][0], cS[2 * ks + 1][1], ph[2], pl[2]);
            split2h(cS[2 * ks + 1][2], cS[2 * ks + 1][3], ph[3], pl[3]);
#pragma unroll
            for (int njp = 0; njp < 4; ++njp) {
                uint32_t v0, v1, v2, v3, w0, w1, w2, w3;
                LDSM4(v0, v1, v2, v3, vb + njp * 2304 + ks * 32);
                LDSM4(w0, w1, w2, w3, vb + 9216 + njp * 2304 + ks * 32);
                uint32_t vA[2] = {v0, v1}, vB[2] = {v2, v3};
                uint32_t wA[2] = {w0, w1}, wB[2] = {w2, w3};
                mma16816(cO[2 * njp], ph, vA);
                mma16816(cO[2 * njp], pl, vA);
                mma16816(cO[2 * njp], ph, wA);
                mma16816(cO[2 * njp + 1], ph, vB);
                mma16816(cO[2 * njp + 1], pl, vB);
                mma16816(cO[2 * njp + 1], ph, wB);
            }
        }
    }

    // ---- epilogue: normalize, split to fp16 hi/lo for proj GEMM ----
    const float i0 = 1.f / lrow[0];
    const float i1 = 1.f / lrow[1];
    const int q0 = qbase + wid * 16 + g;
    const int b = bh >> 4, hh = bh & 15;
    const size_t o0 = (size_t)(b * T_ + q0) * D_ + hh * 64 + 2 * t;
    const size_t o1 = o0 + (size_t)8 * D_;
#pragma unroll
    for (int nj = 0; nj < 8; ++nj) {
        uint32_t hi, lo;
        split2h(cO[nj][0] * i0, cO[nj][1] * i0, hi, lo);
        *(uint32_t*)(g_Oh + o0 + nj * 8) = hi;
        *(uint32_t*)(g_Ol + o0 + nj * 8) = lo;
        split2h(cO[nj][2] * i1, cO[nj][3] * i1, hi, lo);
        *(uint32_t*)(g_Oh + o1 + nj * 8) = hi;
        *(uint32_t*)(g_Ol + o1 + nj * 8) = lo;
    }
}

// =====================================================================
extern "C" void kernel_launch(void* const* d_in, const int* in_sizes, int n_in,
                              void* d_out, int out_size)
{
    const float* x     = (const float*)d_in[0];
    const float* Wqkv  = (const float*)d_in[1];
    const float* Wproj = (const float*)d_in[2];
    const float* bproj = (const float*)d_in[3];
    float* out = (float*)d_out;
    (void)in_sizes; (void)n_in; (void)out_size;

    cudaFuncSetAttribute(gemm_mma<0>, cudaFuncAttributeMaxDynamicSharedMemorySize, G_SMEM);
    cudaFuncSetAttribute(gemm_mma<1>, cudaFuncAttributeMaxDynamicSharedMemorySize, G_SMEM);
    cudaFuncSetAttribute(flash_mma,   cudaFuncAttributeMaxDynamicSharedMemorySize, FA_SMEM);

    convert_in<<<(unsigned)((CX + CQ + CP) / 256), 256>>>(x, Wqkv, Wproj);

    dim3 gq(N_QKV / 128, M1 / 128);   // 24 x 64
    gemm_mma<0><<<gq, 256, G_SMEM>>>(nullptr, nullptr);

    dim3 gt(T_ / 64, B_ * H_);        // 32 x 64
    transpose_v<<<gt, 256>>>();

    dim3 ga(T_ / 128, B_ * H_);       // 16 x 64
    flash_mma<<<ga, 256, FA_SMEM>>>();

    dim3 gp(D_ / 128, M1 / 128);      // 8 x 64
    gemm_mma<1><<<gp, 256, G_SMEM>>>(bproj, out);
}

// round 8
// speedup vs baseline: 4.0741x; 1.2266x over previous
#include <cuda_runtime.h>
#include <cuda_fp16.h>
#include <cstdint>

#define DEVINLINE __device__ __forceinline__

constexpr int B_  = 4;
constexpr int T_  = 2048;
constexpr int D_  = 1024;
constexpr int H_  = 16;
constexpr int HD_ = 64;
constexpr int M1  = B_ * T_;              // 8192
constexpr int N_QKV = 3 * D_;             // 3072
constexpr size_t NE = (size_t)M1 * D_;    // 8388608

// ---- scratch (static __device__; no allocation allowed) ----
__device__ __half g_xh[NE], g_xl[NE];
__device__ __half g_wqh[(size_t)N_QKV * D_];
__device__ __half g_wph[(size_t)D_ * D_];
__device__ __half g_Qh[NE], g_Ql[NE], g_Kh[NE];
__device__ float  g_Vf[NE];
__device__ __half g_Vth[NE], g_Vtl[NE];
__device__ __half g_Oh[NE], g_Ol[NE];

// =====================================================================
// helpers (arch-portable PTX only: mma.sync/ldmatrix/cp.async)
// =====================================================================
DEVINLINE uint32_t smem_u32(const void* p) {
    uint32_t a;
    asm("{ .reg .u64 t; cvta.to.shared.u64 t, %1; cvt.u32.u64 %0, t; }" : "=r"(a) : "l"(p));
    return a;
}
DEVINLINE float ex2f(float x) {
    float y; asm("ex2.approx.ftz.f32 %0, %1;" : "=f"(y) : "f"(x)); return y;
}
DEVINLINE uint32_t pack2h(float x, float y) {
    __half2 h = __floats2half2_rn(x, y);
    return *reinterpret_cast<uint32_t*>(&h);
}
DEVINLINE void split2h(float x, float y, uint32_t& hi, uint32_t& lo) {
    __half hx = __float2half_rn(x), hy = __float2half_rn(y);
    hi = ((uint32_t)__half_as_ushort(hy) << 16) | (uint32_t)__half_as_ushort(hx);
    lo = pack2h(x - __half2float(hx), y - __half2float(hy));
}
DEVINLINE void mma16816(float c[4], const uint32_t a[4], const uint32_t b[2]) {
    asm volatile(
        "mma.sync.aligned.m16n8k16.row.col.f32.f16.f16.f32 "
        "{%0,%1,%2,%3}, {%4,%5,%6,%7}, {%8,%9}, {%0,%1,%2,%3};"
        : "+f"(c[0]), "+f"(c[1]), "+f"(c[2]), "+f"(c[3])
        : "r"(a[0]), "r"(a[1]), "r"(a[2]), "r"(a[3]), "r"(b[0]), "r"(b[1]));
}
#define LDSM4(r0, r1, r2, r3, addr)                                           \
    asm volatile("ldmatrix.sync.aligned.m8n8.x4.shared.b16 {%0,%1,%2,%3}, [%4];" \
        : "=r"(r0), "=r"(r1), "=r"(r2), "=r"(r3) : "r"(addr))
DEVINLINE void ldsm4a(uint32_t r[4], uint32_t addr) { LDSM4(r[0], r[1], r[2], r[3], addr); }
DEVINLINE void cp16(uint32_t dst, const void* src) {
    asm volatile("cp.async.cg.shared.global [%0], [%1], 16;" :: "r"(dst), "l"(src));
}
#define CP_COMMIT() asm volatile("cp.async.commit_group;" ::: "memory")
#define CP_WAIT0()  asm volatile("cp.async.wait_group 0;" ::: "memory")
#define CP_WAIT2()  asm volatile("cp.async.wait_group 2;" ::: "memory")

// =====================================================================
// convert inputs: x -> (hi,lo) fp16; W_qkv, W_proj -> hi fp16
// =====================================================================
constexpr size_t CX = NE / 4;
constexpr size_t CQ = (size_t)N_QKV * D_ / 4;
constexpr size_t CP = (size_t)D_ * D_ / 4;
__global__ void convert_in(const float* __restrict__ x, const float* __restrict__ wq,
                           const float* __restrict__ wp)
{
    size_t i = (size_t)blockIdx.x * 256 + threadIdx.x;
    if (i < CX) {
        float4 v = ((const float4*)x)[i];
        uint32_t h0, l0, h1, l1;
        split2h(v.x, v.y, h0, l0);
        split2h(v.z, v.w, h1, l1);
        ((uint2*)g_xh)[i] = make_uint2(h0, h1);
        ((uint2*)g_xl)[i] = make_uint2(l0, l1);
    } else if (i < CX + CQ) {
        size_t j = i - CX;
        float4 v = ((const float4*)wq)[j];
        ((uint2*)g_wqh)[j] = make_uint2(pack2h(v.x, v.y), pack2h(v.z, v.w));
    } else {
        size_t j = i - CX - CQ;
        float4 v = ((const float4*)wp)[j];
        ((uint2*)g_wph)[j] = make_uint2(pack2h(v.x, v.y), pack2h(v.z, v.w));
    }
}

// =====================================================================
// transpose V: g_Vf [bh][t][d] fp32 -> g_Vth/g_Vtl [bh][d][t] fp16
// =====================================================================
__global__ void transpose_v()
{
    __shared__ float ts[64][65];
    const int bh = blockIdx.y, tt = blockIdx.x, tid = threadIdx.x;
    const float* src = g_Vf + (size_t)bh * T_ * HD_ + (size_t)tt * 64 * HD_;
#pragma unroll
    for (int u = 0; u < 4; ++u) {
        int idx = tid + 256 * u;
        int r = idx >> 4, c4 = (idx & 15) * 4;
        float4 v = *(const float4*)(src + r * HD_ + c4);
        ts[r][c4] = v.x; ts[r][c4 + 1] = v.y; ts[r][c4 + 2] = v.z; ts[r][c4 + 3] = v.w;
    }
    __syncthreads();
#pragma unroll
    for (int u = 0; u < 8; ++u) {
        int idx = tid + 256 * u;
        int d = idx >> 5, tp = (idx & 31) * 2;
        uint32_t hi, lo;
        split2h(ts[tp][d], ts[tp + 1][d], hi, lo);
        size_t o = (size_t)bh * T_ * HD_ + (size_t)d * T_ + tt * 64 + tp;
        *(uint32_t*)(g_Vth + o) = hi;
        *(uint32_t*)(g_Vtl + o) = lo;
    }
}

// =====================================================================
// HMMA GEMM (fp16 2-term). Tile 128x128x16, 8 warps, cp.async 4-stage,
// ldmatrix fragments.  MODE 0: Q (pre-scaled, hi/lo), K (hi), V (f32).
// MODE 1: out = A*W^T + bias.
// =====================================================================
constexpr int STG_B = 18432;
constexpr int G_SMEM = 4 * STG_B;
constexpr float SC_Q = 0.18033688011112042385f;   // log2(e)/sqrt(64)

template <int MODE>
__global__ __launch_bounds__(256, 2)
void gemm_mma(const float* __restrict__ bias, float* __restrict__ Cout)
{
    extern __shared__ __align__(16) char smg[];
    const uint32_t sb = smem_u32(smg);
    const __half* Ah = (MODE == 0) ? g_xh : g_Oh;
    const __half* Al = (MODE == 0) ? g_xl : g_Ol;
    const __half* Bh = (MODE == 0) ? g_wqh : g_wph;

    const int tid = threadIdx.x, lane = tid & 31, wid = tid >> 5;
    const int g = lane >> 2, t = lane & 3;
    const int wm = wid >> 1, wn = wid & 1;
    const int bm = blockIdx.y * 128, bn = blockIdx.x * 128;

    float c[2][8][4];
#pragma unroll
    for (int i = 0; i < 2; ++i)
#pragma unroll
        for (int j = 0; j < 8; ++j)
#pragma unroll
            for (int k = 0; k < 4; ++k) c[i][j][k] = 0.f;

    const int ldrow = tid >> 1, ldh = (tid & 1) * 8;
    auto issue = [&](int s, int kt) {
        const uint32_t dst = sb + s * STG_B + ldrow * 48 + ldh * 2;
        const int k0 = kt * 16 + ldh;
        cp16(dst,         Ah + (size_t)(bm + ldrow) * D_ + k0);
        cp16(dst + 6144,  Al + (size_t)(bm + ldrow) * D_ + k0);
        cp16(dst + 12288, Bh + (size_t)(bn + ldrow) * D_ + k0);
    };

    const uint32_t aoff = (uint32_t)((wm * 32 + (lane & 7) + (lane & 8)) * 48 + (lane >> 4) * 16);
    const uint32_t boff = (uint32_t)(12288 + (wn * 64 + (lane & 7) + ((lane >> 1) & 8)) * 48 + (lane & 8) * 2);

#pragma unroll 1
    for (int s = 0; s < 3; ++s) { issue(s, s); CP_COMMIT(); }

    constexpr int NT = D_ / 16;
    for (int kt = 0; kt < NT; ++kt) {
        CP_WAIT2();
        __syncthreads();
        if (kt + 3 < NT) issue((kt + 3) & 3, kt + 3);
        CP_COMMIT();

        const uint32_t stb = sb + (kt & 3) * STG_B;
        uint32_t ah[2][4], al[2][4];
        ldsm4a(ah[0], stb + aoff);
        ldsm4a(ah[1], stb + aoff + 768);
        ldsm4a(al[0], stb + aoff + 6144);
        ldsm4a(al[1], stb + aoff + 6912);
#pragma unroll
        for (int njp = 0; njp < 4; ++njp) {
            uint32_t b0, b1, b2, b3;
            LDSM4(b0, b1, b2, b3, stb + boff + njp * 768);
            uint32_t bA[2] = {b0, b1}, bB[2] = {b2, b3};
            mma16816(c[0][2 * njp], ah[0], bA);
            mma16816(c[0][2 * njp], al[0], bA);
            mma16816(c[1][2 * njp], ah[1], bA);
            mma16816(c[1][2 * njp], al[1], bA);
            mma16816(c[0][2 * njp + 1], ah[0], bB);
            mma16816(c[0][2 * njp + 1], al[0], bB);
            mma16816(c[1][2 * njp + 1], ah[1], bB);
            mma16816(c[1][2 * njp + 1], al[1], bB);
        }
    }

    // epilogue
#pragma unroll
    for (int mi = 0; mi < 2; ++mi) {
        const int r0 = bm + wm * 32 + mi * 16 + g;
        const int r1 = r0 + 8;
#pragma unroll
        for (int nj = 0; nj < 8; ++nj) {
            const int cn = bn + wn * 64 + nj * 8 + 2 * t;
            if (MODE == 0) {
                const int part = cn >> 10, hh = (cn >> 6) & 15, dd = cn & 63;
                const int bb0 = r0 >> 11, tt0 = r0 & 2047;
                const int bb1 = r1 >> 11, tt1 = r1 & 2047;
                const size_t o0 = (((size_t)(bb0 * H_ + hh) * T_ + tt0) << 6) + dd;
                const size_t o1 = (((size_t)(bb1 * H_ + hh) * T_ + tt1) << 6) + dd;
                if (part == 2) {
                    *(float2*)&g_Vf[o0] = make_float2(c[mi][nj][0], c[mi][nj][1]);
                    *(float2*)&g_Vf[o1] = make_float2(c[mi][nj][2], c[mi][nj][3]);
                } else if (part == 0) {
                    uint32_t hi, lo;
                    split2h(c[mi][nj][0] * SC_Q, c[mi][nj][1] * SC_Q, hi, lo);
                    *(uint32_t*)(g_Qh + o0) = hi; *(uint32_t*)(g_Ql + o0) = lo;
                    split2h(c[mi][nj][2] * SC_Q, c[mi][nj][3] * SC_Q, hi, lo);
                    *(uint32_t*)(g_Qh + o1) = hi; *(uint32_t*)(g_Ql + o1) = lo;
                } else {
                    *(uint32_t*)(g_Kh + o0) = pack2h(c[mi][nj][0], c[mi][nj][1]);
                    *(uint32_t*)(g_Kh + o1) = pack2h(c[mi][nj][2], c[mi][nj][3]);
                }
            } else {
                float2 bv = *(const float2*)&bias[cn];
                *(float2*)&Cout[(size_t)r0 * D_ + cn] =
                    make_float2(c[mi][nj][0] + bv.x, c[mi][nj][1] + bv.y);
                *(float2*)&Cout[(size_t)r1 * D_ + cn] =
                    make_float2(c[mi][nj][2] + bv.x, c[mi][nj][3] + bv.y);
            }
        }
    }
}

// =====================================================================
// HMMA flash attention, causal.  q-tile 64, 4 warps, 3 CTAs/SM.
// QK 2-term (Qh+Ql)*Kh; P in fp16 (f32 EX2 then pack); PV = Ph*(Vh+Vl);
// row-sum l via all-ones MMA column.  Q pre-scaled by log2e/8.
// smem: 2 KV stages of [Kh|Vth|Vtl], 64 rows x 144B each.
// =====================================================================
constexpr int KSTG = 3 * 64 * 144;        // 27648
constexpr int FA_SMEM = 2 * KSTG;         // 55296

__global__ __launch_bounds__(128, 3)
void flash_mma()
{
    extern __shared__ __align__(16) char sma[];
    const uint32_t sb = smem_u32(sma);
    const int tid = threadIdx.x, lane = tid & 31, wid = tid >> 5;
    const int g = lane >> 2, t = lane & 3;
    const int qt = blockIdx.x, bh = blockIdx.y;
    const int qbase = qt * 64;
    const int nkt = qt + 1;

    const size_t hb = (size_t)bh * T_ * HD_;
    const __half* Qhp = g_Qh + hb; const __half* Qlp = g_Ql + hb;
    const __half* Khp = g_Kh + hb;
    const __half* Vhp = g_Vth + hb; const __half* Vlp = g_Vtl + hb;

    const float NEG_INF = __int_as_float(0xff800000);

    // ---- stage Q (Qh at sb, Ql at sb+9216), hoist fragments ----
#pragma unroll
    for (int u = 0; u < 8; ++u) {
        int cidx = u * 128 + tid;
        int arr = cidx >> 9, row = (cidx >> 3) & 63, ch = cidx & 7;
        cp16(sb + arr * 9216 + row * 144 + ch * 16,
             (arr ? Qlp : Qhp) + (size_t)(qbase + row) * HD_ + ch * 8);
    }
    CP_COMMIT(); CP_WAIT0(); __syncthreads();

    uint32_t qh[4][4], ql[4][4];
    {
        const uint32_t qb = sb + (wid * 16 + (lane & 7) + (lane & 8)) * 144 + (lane >> 4) * 16;
#pragma unroll
        for (int ks = 0; ks < 4; ++ks) {
            ldsm4a(qh[ks], qb + ks * 32);
            ldsm4a(ql[ks], qb + 9216 + ks * 32);
        }
    }
    __syncthreads();

    auto issueKV = [&](int s, int kt) {
        const int ktb = kt * 64;
#pragma unroll
        for (int u = 0; u < 12; ++u) {
            int cidx = u * 128 + tid;
            int arr = cidx >> 9, row = (cidx >> 3) & 63, ch = cidx & 7;
            uint32_t dst = sb + s * KSTG + arr * 9216 + row * 144 + ch * 16;
            const __half* src;
            if (arr == 0)      src = Khp + (size_t)(ktb + row) * HD_ + ch * 8;
            else if (arr == 1) src = Vhp + (size_t)row * T_ + ktb + ch * 8;
            else               src = Vlp + (size_t)row * T_ + ktb + ch * 8;
            cp16(dst, src);
        }
    };

    float cO[8][4];
#pragma unroll
    for (int j = 0; j < 8; ++j)
#pragma unroll
        for (int k = 0; k < 4; ++k) cO[j][k] = 0.f;
    float mrow[2] = {NEG_INF, NEG_INF};
    float lrow[2] = {0.f, 0.f};

    issueKV(0, 0); CP_COMMIT();

    const uint32_t frow = (uint32_t)(((lane & 7) + ((lane >> 1) & 8)) * 144 + (lane & 8) * 2);
    const uint32_t ones2 = 0x3C003C00u;
    const uint32_t onesb[2] = {ones2, ones2};

    for (int kt = 0; kt < nkt; ++kt) {
        CP_WAIT0();
        __syncthreads();
        if (kt + 1 < nkt) issueKV((kt + 1) & 1, kt + 1);
        CP_COMMIT();

        const uint32_t stb = sb + (kt & 1) * KSTG;

        // ---- S = Q K^T (2-term; Q pre-scaled to log2 units) ----
        float cS[8][4];
#pragma unroll
        for (int j = 0; j < 8; ++j)
#pragma unroll
            for (int k = 0; k < 4; ++k) cS[j][k] = 0.f;

        const uint32_t kb = stb + frow;
#pragma unroll
        for (int ks = 0; ks < 4; ++ks) {
#pragma unroll
            for (int njp = 0; njp < 4; ++njp) {
                uint32_t b0, b1, b2, b3;
                LDSM4(b0, b1, b2, b3, kb + njp * 2304 + ks * 32);
                uint32_t bA[2] = {b0, b1}, bB[2] = {b2, b3};
                mma16816(cS[2 * njp], qh[ks], bA);
                mma16816(cS[2 * njp], ql[ks], bA);
                mma16816(cS[2 * njp + 1], qh[ks], bB);
                mma16816(cS[2 * njp + 1], ql[ks], bB);
            }
        }

        // ---- causal mask (diagonal tile only) ----
        if (kt == nkt - 1) {
            const int kb0 = kt * 64;
#pragma unroll
            for (int h = 0; h < 2; ++h) {
                const int qrow = qbase + wid * 16 + g + 8 * h;
#pragma unroll
                for (int nj = 0; nj < 8; ++nj)
#pragma unroll
                    for (int cc = 0; cc < 2; ++cc)
                        if (kb0 + nj * 8 + 2 * t + cc > qrow) cS[nj][2 * h + cc] = NEG_INF;
            }
        }

        // ---- online softmax: f32 EX2, pack to fp16 P ----
        uint32_t pH[2][8];
#pragma unroll
        for (int h = 0; h < 2; ++h) {
            float mloc = NEG_INF;
#pragma unroll
            for (int nj = 0; nj < 8; ++nj) {
                mloc = fmaxf(mloc, fmaxf(cS[nj][2 * h], cS[nj][2 * h + 1]));
            }
            mloc = fmaxf(mloc, __shfl_xor_sync(0xffffffffu, mloc, 1));
            mloc = fmaxf(mloc, __shfl_xor_sync(0xffffffffu, mloc, 2));
            const float mnew  = fmaxf(mrow[h], mloc);
            const float alpha = ex2f(mrow[h] - mnew);
            mrow[h] = mnew;
#pragma unroll
            for (int nj = 0; nj < 8; ++nj) {
                float p0 = ex2f(cS[nj][2 * h]     - mnew);
                float p1 = ex2f(cS[nj][2 * h + 1] - mnew);
                pH[h][nj] = pack2h(p0, p1);
            }
            lrow[h] *= alpha;
#pragma unroll
            for (int nj = 0; nj < 8; ++nj) {
                cO[nj][2 * h + 0] *= alpha;
                cO[nj][2 * h + 1] *= alpha;
            }
        }

        // ---- O += P (Vh + Vl); l += P * ones ----
        float cL[4] = {0.f, 0.f, 0.f, 0.f};
        const uint32_t vbh = stb + 9216 + frow;
        const uint32_t vbl = stb + 18432 + frow;
#pragma unroll
        for (int ks = 0; ks < 4; ++ks) {
            uint32_t aP[4] = {pH[0][2 * ks], pH[1][2 * ks],
                              pH[0][2 * ks + 1], pH[1][2 * ks + 1]};
            mma16816(cL, aP, onesb);
#pragma unroll
            for (int njp = 0; njp < 4; ++njp) {
                uint32_t v0, v1, v2, v3, w0, w1, w2, w3;
                LDSM4(v0, v1, v2, v3, vbh + njp * 2304 + ks * 32);
                LDSM4(w0, w1, w2, w3, vbl + njp * 2304 + ks * 32);
                uint32_t vA[2] = {v0, v1}, vB[2] = {v2, v3};
                uint32_t wA[2] = {w0, w1}, wB[2] = {w2, w3};
                mma16816(cO[2 * njp], aP, vA);
                mma16816(cO[2 * njp], aP, wA);
                mma16816(cO[2 * njp + 1], aP, vB);
                mma16816(cO[2 * njp + 1], aP, wB);
            }
        }
        lrow[0] += cL[0];
        lrow[1] += cL[2];
    }

    // ---- epilogue: normalize, split to fp16 hi/lo for proj GEMM ----
    const float i0 = 1.f / lrow[0];
    const float i1 = 1.f / lrow[1];
    const int q0 = qbase + wid * 16 + g;
    const int b = bh >> 4, hh = bh & 15;
    const size_t o0 = (size_t)(b * T_ + q0) * D_ + hh * 64 + 2 * t;
    const size_t o1 = o0 + (size_t)8 * D_;
#pragma unroll
    for (int nj = 0; nj < 8; ++nj) {
        uint32_t hi, lo;
        split2h(cO[nj][0] * i0, cO[nj][1] * i0, hi, lo);
        *(uint32_t*)(g_Oh + o0 + nj * 8) = hi;
        *(uint32_t*)(g_Ol + o0 + nj * 8) = lo;
        split2h(cO[nj][2] * i1, cO[nj][3] * i1, hi, lo);
        *(uint32_t*)(g_Oh + o1 + nj * 8) = hi;
        *(uint32_t*)(g_Ol + o1 + nj * 8) = lo;
    }
}

// =====================================================================
extern "C" void kernel_launch(void* const* d_in, const int* in_sizes, int n_in,
                              void* d_out, int out_size)
{
    const float* x     = (const float*)d_in[0];
    const float* Wqkv  = (const float*)d_in[1];
    const float* Wproj = (const float*)d_in[2];
    const float* bproj = (const float*)d_in[3];
    float* out = (float*)d_out;
    (void)in_sizes; (void)n_in; (void)out_size;

    cudaFuncSetAttribute(gemm_mma<0>, cudaFuncAttributeMaxDynamicSharedMemorySize, G_SMEM);
    cudaFuncSetAttribute(gemm_mma<1>, cudaFuncAttributeMaxDynamicSharedMemorySize, G_SMEM);
    cudaFuncSetAttribute(flash_mma,   cudaFuncAttributeMaxDynamicSharedMemorySize, FA_SMEM);

    convert_in<<<(unsigned)((CX + CQ + CP) / 256), 256>>>(x, Wqkv, Wproj);

    dim3 gq(N_QKV / 128, M1 / 128);   // 24 x 64
    gemm_mma<0><<<gq, 256, G_SMEM>>>(nullptr, nullptr);

    dim3 gt(T_ / 64, B_ * H_);        // 32 x 64
    transpose_v<<<gt, 256>>>();

    dim3 ga(T_ / 64, B_ * H_);        // 32 x 64
    flash_mma<<<ga, 128, FA_SMEM>>>();

    dim3 gp(D_ / 128, M1 / 128);      // 8 x 64
    gemm_mma<1><<<gp, 256, G_SMEM>>>(bproj, out);
}

// round 9
// speedup vs baseline: 5.1803x; 1.2715x over previous
#include <cuda_runtime.h>
#include <cuda_fp16.h>
#include <cstdint>

#define DEVINLINE __device__ __forceinline__

constexpr int B_  = 4;
constexpr int T_  = 2048;
constexpr int D_  = 1024;
constexpr int H_  = 16;
constexpr int HD_ = 64;
constexpr int M1  = B_ * T_;              // 8192
constexpr int N_QKV = 3 * D_;             // 3072
constexpr size_t NE = (size_t)M1 * D_;    // 8388608

// ---- scratch (static __device__; no allocation allowed) ----
__device__ __half g_xh[NE], g_xl[NE];
__device__ __half g_wqh[(size_t)N_QKV * D_];
__device__ __half g_wph[(size_t)D_ * D_];
__device__ __half g_Qh[NE], g_Kh[NE];
__device__ float  g_Vf[NE];
__device__ __half g_Vth[NE];
__device__ __half g_Oh[NE], g_Ol[NE];

// =====================================================================
// helpers (arch-portable PTX only: mma.sync/ldmatrix/cp.async)
// =====================================================================
DEVINLINE uint32_t smem_u32(const void* p) {
    uint32_t a;
    asm("{ .reg .u64 t; cvta.to.shared.u64 t, %1; cvt.u32.u64 %0, t; }" : "=r"(a) : "l"(p));
    return a;
}
DEVINLINE float ex2f(float x) {
    float y; asm("ex2.approx.ftz.f32 %0, %1;" : "=f"(y) : "f"(x)); return y;
}
DEVINLINE uint32_t pack2h(float x, float y) {
    __half2 h = __floats2half2_rn(x, y);
    return *reinterpret_cast<uint32_t*>(&h);
}
DEVINLINE void split2h(float x, float y, uint32_t& hi, uint32_t& lo) {
    __half hx = __float2half_rn(x), hy = __float2half_rn(y);
    hi = ((uint32_t)__half_as_ushort(hy) << 16) | (uint32_t)__half_as_ushort(hx);
    lo = pack2h(x - __half2float(hx), y - __half2float(hy));
}
DEVINLINE void mma16816(float c[4], const uint32_t a[4], const uint32_t b[2]) {
    asm volatile(
        "mma.sync.aligned.m16n8k16.row.col.f32.f16.f16.f32 "
        "{%0,%1,%2,%3}, {%4,%5,%6,%7}, {%8,%9}, {%0,%1,%2,%3};"
        : "+f"(c[0]), "+f"(c[1]), "+f"(c[2]), "+f"(c[3])
        : "r"(a[0]), "r"(a[1]), "r"(a[2]), "r"(a[3]), "r"(b[0]), "r"(b[1]));
}
#define LDSM4(r0, r1, r2, r3, addr)                                           \
    asm volatile("ldmatrix.sync.aligned.m8n8.x4.shared.b16 {%0,%1,%2,%3}, [%4];" \
        : "=r"(r0), "=r"(r1), "=r"(r2), "=r"(r3) : "r"(addr))
DEVINLINE void ldsm4a(uint32_t r[4], uint32_t addr) { LDSM4(r[0], r[1], r[2], r[3], addr); }
DEVINLINE void cp16(uint32_t dst, const void* src) {
    asm volatile("cp.async.cg.shared.global [%0], [%1], 16;" :: "r"(dst), "l"(src));
}
#define CP_COMMIT() asm volatile("cp.async.commit_group;" ::: "memory")
#define CP_WAIT0()  asm volatile("cp.async.wait_group 0;" ::: "memory")
#define CP_WAIT2()  asm volatile("cp.async.wait_group 2;" ::: "memory")

// =====================================================================
// convert inputs: x -> (hi,lo) fp16; W_qkv, W_proj -> hi fp16
// =====================================================================
constexpr size_t CX = NE / 4;
constexpr size_t CQ = (size_t)N_QKV * D_ / 4;
constexpr size_t CP = (size_t)D_ * D_ / 4;
__global__ void convert_in(const float* __restrict__ x, const float* __restrict__ wq,
                           const float* __restrict__ wp)
{
    size_t i = (size_t)blockIdx.x * 256 + threadIdx.x;
    if (i < CX) {
        float4 v = ((const float4*)x)[i];
        uint32_t h0, l0, h1, l1;
        split2h(v.x, v.y, h0, l0);
        split2h(v.z, v.w, h1, l1);
        ((uint2*)g_xh)[i] = make_uint2(h0, h1);
        ((uint2*)g_xl)[i] = make_uint2(l0, l1);
    } else if (i < CX + CQ) {
        size_t j = i - CX;
        float4 v = ((const float4*)wq)[j];
        ((uint2*)g_wqh)[j] = make_uint2(pack2h(v.x, v.y), pack2h(v.z, v.w));
    } else {
        size_t j = i - CX - CQ;
        float4 v = ((const float4*)wp)[j];
        ((uint2*)g_wph)[j] = make_uint2(pack2h(v.x, v.y), pack2h(v.z, v.w));
    }
}

// =====================================================================
// transpose V: g_Vf [bh][t][d] fp32 -> g_Vth [bh][d][t] fp16 (hi only)
// =====================================================================
__global__ void transpose_v()
{
    __shared__ float ts[64][65];
    const int bh = blockIdx.y, tt = blockIdx.x, tid = threadIdx.x;
    const float* src = g_Vf + (size_t)bh * T_ * HD_ + (size_t)tt * 64 * HD_;
#pragma unroll
    for (int u = 0; u < 4; ++u) {
        int idx = tid + 256 * u;
        int r = idx >> 4, c4 = (idx & 15) * 4;
        float4 v = *(const float4*)(src + r * HD_ + c4);
        ts[r][c4] = v.x; ts[r][c4 + 1] = v.y; ts[r][c4 + 2] = v.z; ts[r][c4 + 3] = v.w;
    }
    __syncthreads();
#pragma unroll
    for (int u = 0; u < 8; ++u) {
        int idx = tid + 256 * u;
        int d = idx >> 5, tp = (idx & 31) * 2;
        size_t o = (size_t)bh * T_ * HD_ + (size_t)d * T_ + tt * 64 + tp;
        *(uint32_t*)(g_Vth + o) = pack2h(ts[tp][d], ts[tp + 1][d]);
    }
}

// =====================================================================
// HMMA GEMM. Tile 128x128x16, 8 warps, cp.async 4-stage, ldmatrix.
// MODE 0: Q/K blocks (bx<16) 1-term xh*Wh; V blocks (bx>=16) 2-term.
//         Q pre-scaled -> g_Qh; K -> g_Kh; V -> g_Vf (f32).
// MODE 1: 2-term (Oh+Ol)*Wph + bias -> out.
// =====================================================================
constexpr int STG_B = 18432;
constexpr int G_SMEM = 4 * STG_B;
constexpr float SC_Q = 0.18033688011112042385f;   // log2(e)/sqrt(64)

template <int MODE>
__global__ __launch_bounds__(256, 2)
void gemm_mma(const float* __restrict__ bias, float* __restrict__ Cout)
{
    extern __shared__ __align__(16) char smg[];
    const uint32_t sb = smem_u32(smg);
    const __half* Ah = (MODE == 0) ? g_xh : g_Oh;
    const __half* Al = (MODE == 0) ? g_xl : g_Ol;
    const __half* Bh = (MODE == 0) ? g_wqh : g_wph;
    const bool two = (MODE == 1) || (blockIdx.x >= 16);

    const int tid = threadIdx.x, lane = tid & 31, wid = tid >> 5;
    const int g = lane >> 2, t = lane & 3;
    const int wm = wid >> 1, wn = wid & 1;
    const int bm = blockIdx.y * 128, bn = blockIdx.x * 128;

    float c[2][8][4];
#pragma unroll
    for (int i = 0; i < 2; ++i)
#pragma unroll
        for (int j = 0; j < 8; ++j)
#pragma unroll
            for (int k = 0; k < 4; ++k) c[i][j][k] = 0.f;

    const int ldrow = tid >> 1, ldh = (tid & 1) * 8;
    auto issue = [&](int s, int kt) {
        const uint32_t dst = sb + s * STG_B + ldrow * 48 + ldh * 2;
        const int k0 = kt * 16 + ldh;
        cp16(dst,         Ah + (size_t)(bm + ldrow) * D_ + k0);
        if (two) cp16(dst + 6144, Al + (size_t)(bm + ldrow) * D_ + k0);
        cp16(dst + 12288, Bh + (size_t)(bn + ldrow) * D_ + k0);
    };

    const uint32_t aoff = (uint32_t)((wm * 32 + (lane & 7) + (lane & 8)) * 48 + (lane >> 4) * 16);
    const uint32_t boff = (uint32_t)(12288 + (wn * 64 + (lane & 7) + ((lane >> 1) & 8)) * 48 + (lane & 8) * 2);

#pragma unroll 1
    for (int s = 0; s < 3; ++s) { issue(s, s); CP_COMMIT(); }

    constexpr int NT = D_ / 16;
    for (int kt = 0; kt < NT; ++kt) {
        CP_WAIT2();
        __syncthreads();
        if (kt + 3 < NT) issue((kt + 3) & 3, kt + 3);
        CP_COMMIT();

        const uint32_t stb = sb + (kt & 3) * STG_B;
        uint32_t ah[2][4], al[2][4];
        ldsm4a(ah[0], stb + aoff);
        ldsm4a(ah[1], stb + aoff + 768);
        if (two) {
            ldsm4a(al[0], stb + aoff + 6144);
            ldsm4a(al[1], stb + aoff + 6912);
        }
#pragma unroll
        for (int njp = 0; njp < 4; ++njp) {
            uint32_t b0, b1, b2, b3;
            LDSM4(b0, b1, b2, b3, stb + boff + njp * 768);
            uint32_t bA[2] = {b0, b1}, bB[2] = {b2, b3};
            mma16816(c[0][2 * njp], ah[0], bA);
            mma16816(c[1][2 * njp], ah[1], bA);
            mma16816(c[0][2 * njp + 1], ah[0], bB);
            mma16816(c[1][2 * njp + 1], ah[1], bB);
            if (two) {
                mma16816(c[0][2 * njp], al[0], bA);
                mma16816(c[1][2 * njp], al[1], bA);
                mma16816(c[0][2 * njp + 1], al[0], bB);
                mma16816(c[1][2 * njp + 1], al[1], bB);
            }
        }
    }

    // epilogue
#pragma unroll
    for (int mi = 0; mi < 2; ++mi) {
        const int r0 = bm + wm * 32 + mi * 16 + g;
        const int r1 = r0 + 8;
#pragma unroll
        for (int nj = 0; nj < 8; ++nj) {
            const int cn = bn + wn * 64 + nj * 8 + 2 * t;
            if (MODE == 0) {
                const int part = cn >> 10, hh = (cn >> 6) & 15, dd = cn & 63;
                const int bb0 = r0 >> 11, tt0 = r0 & 2047;
                const int bb1 = r1 >> 11, tt1 = r1 & 2047;
                const size_t o0 = (((size_t)(bb0 * H_ + hh) * T_ + tt0) << 6) + dd;
                const size_t o1 = (((size_t)(bb1 * H_ + hh) * T_ + tt1) << 6) + dd;
                if (part == 2) {
                    *(float2*)&g_Vf[o0] = make_float2(c[mi][nj][0], c[mi][nj][1]);
                    *(float2*)&g_Vf[o1] = make_float2(c[mi][nj][2], c[mi][nj][3]);
                } else if (part == 0) {
                    *(uint32_t*)(g_Qh + o0) = pack2h(c[mi][nj][0] * SC_Q, c[mi][nj][1] * SC_Q);
                    *(uint32_t*)(g_Qh + o1) = pack2h(c[mi][nj][2] * SC_Q, c[mi][nj][3] * SC_Q);
                } else {
                    *(uint32_t*)(g_Kh + o0) = pack2h(c[mi][nj][0], c[mi][nj][1]);
                    *(uint32_t*)(g_Kh + o1) = pack2h(c[mi][nj][2], c[mi][nj][3]);
                }
            } else {
                float2 bv = *(const float2*)&bias[cn];
                *(float2*)&Cout[(size_t)r0 * D_ + cn] =
                    make_float2(c[mi][nj][0] + bv.x, c[mi][nj][1] + bv.y);
                *(float2*)&Cout[(size_t)r1 * D_ + cn] =
                    make_float2(c[mi][nj][2] + bv.x, c[mi][nj][3] + bv.y);
            }
        }
    }
}

// =====================================================================
// HMMA flash attention, causal. q-tile 64, 4 warps.
// QK 1-term Qh*Kh (Q pre-scaled, log2 units); P fp16; PV 1-term Ph*Vh;
// row-sum l via all-ones MMA column.
// smem: 2 KV stages of [Kh|Vth], 64 rows x 144B each.
// =====================================================================
constexpr int KSTG = 2 * 64 * 144;        // 18432
constexpr int FA_SMEM = 2 * KSTG;         // 36864

__global__ __launch_bounds__(128, 3)
void flash_mma()
{
    extern __shared__ __align__(16) char sma[];
    const uint32_t sb = smem_u32(sma);
    const int tid = threadIdx.x, lane = tid & 31, wid = tid >> 5;
    const int g = lane >> 2, t = lane & 3;
    const int qt = blockIdx.x, bh = blockIdx.y;
    const int qbase = qt * 64;
    const int nkt = qt + 1;

    const size_t hb = (size_t)bh * T_ * HD_;
    const __half* Qhp = g_Qh + hb;
    const __half* Khp = g_Kh + hb;
    const __half* Vhp = g_Vth + hb;

    const float NEG_INF = __int_as_float(0xff800000);

    // ---- stage Q, hoist fragments ----
#pragma unroll
    for (int u = 0; u < 4; ++u) {
        int cidx = u * 128 + tid;
        int row = (cidx >> 3) & 63, ch = cidx & 7;
        cp16(sb + row * 144 + ch * 16, Qhp + (size_t)(qbase + row) * HD_ + ch * 8);
    }
    CP_COMMIT(); CP_WAIT0(); __syncthreads();

    uint32_t qh[4][4];
    {
        const uint32_t qb = sb + (wid * 16 + (lane & 7) + (lane & 8)) * 144 + (lane >> 4) * 16;
#pragma unroll
        for (int ks = 0; ks < 4; ++ks) ldsm4a(qh[ks], qb + ks * 32);
    }
    __syncthreads();

    auto issueKV = [&](int s, int kt) {
        const int ktb = kt * 64;
#pragma unroll
        for (int u = 0; u < 8; ++u) {
            int cidx = u * 128 + tid;
            int arr = cidx >> 9, row = (cidx >> 3) & 63, ch = cidx & 7;
            uint32_t dst = sb + s * KSTG + arr * 9216 + row * 144 + ch * 16;
            const __half* src = (arr == 0)
                ? Khp + (size_t)(ktb + row) * HD_ + ch * 8
                : Vhp + (size_t)row * T_ + ktb + ch * 8;
            cp16(dst, src);
        }
    };

    float cO[8][4];
#pragma unroll
    for (int j = 0; j < 8; ++j)
#pragma unroll
        for (int k = 0; k < 4; ++k) cO[j][k] = 0.f;
    float mrow[2] = {NEG_INF, NEG_INF};
    float lrow[2] = {0.f, 0.f};

    issueKV(0, 0); CP_COMMIT();

    const uint32_t frow = (uint32_t)(((lane & 7) + ((lane >> 1) & 8)) * 144 + (lane & 8) * 2);
    const uint32_t ones2 = 0x3C003C00u;
    const uint32_t onesb[2] = {ones2, ones2};

    for (int kt = 0; kt < nkt; ++kt) {
        CP_WAIT0();
        __syncthreads();
        if (kt + 1 < nkt) issueKV((kt + 1) & 1, kt + 1);
        CP_COMMIT();

        const uint32_t stb = sb + (kt & 1) * KSTG;

        // ---- S = Q K^T (1-term; Q pre-scaled to log2 units) ----
        float cS[8][4];
#pragma unroll
        for (int j = 0; j < 8; ++j)
#pragma unroll
            for (int k = 0; k < 4; ++k) cS[j][k] = 0.f;

        const uint32_t kb = stb + frow;
#pragma unroll
        for (int ks = 0; ks < 4; ++ks) {
#pragma unroll
            for (int njp = 0; njp < 4; ++njp) {
                uint32_t b0, b1, b2, b3;
                LDSM4(b0, b1, b2, b3, kb + njp * 2304 + ks * 32);
                uint32_t bA[2] = {b0, b1}, bB[2] = {b2, b3};
                mma16816(cS[2 * njp], qh[ks], bA);
                mma16816(cS[2 * njp + 1], qh[ks], bB);
            }
        }

        // ---- causal mask (diagonal tile only) ----
        if (kt == nkt - 1) {
            const int kb0 = kt * 64;
#pragma unroll
            for (int h = 0; h < 2; ++h) {
                const int qrow = qbase + wid * 16 + g + 8 * h;
#pragma unroll
                for (int nj = 0; nj < 8; ++nj)
#pragma unroll
                    for (int cc = 0; cc < 2; ++cc)
                        if (kb0 + nj * 8 + 2 * t + cc > qrow) cS[nj][2 * h + cc] = NEG_INF;
            }
        }

        // ---- online softmax: f32 EX2, pack to fp16 P ----
        uint32_t pH[2][8];
#pragma unroll
        for (int h = 0; h < 2; ++h) {
            float mloc = NEG_INF;
#pragma unroll
            for (int nj = 0; nj < 8; ++nj)
                mloc = fmaxf(mloc, fmaxf(cS[nj][2 * h], cS[nj][2 * h + 1]));
            mloc = fmaxf(mloc, __shfl_xor_sync(0xffffffffu, mloc, 1));
            mloc = fmaxf(mloc, __shfl_xor_sync(0xffffffffu, mloc, 2));
            const float mnew  = fmaxf(mrow[h], mloc);
            const float alpha = ex2f(mrow[h] - mnew);
            mrow[h] = mnew;
#pragma unroll
            for (int nj = 0; nj < 8; ++nj) {
                float p0 = ex2f(cS[nj][2 * h]     - mnew);
                float p1 = ex2f(cS[nj][2 * h + 1] - mnew);
                pH[h][nj] = pack2h(p0, p1);
            }
            lrow[h] *= alpha;
#pragma unroll
            for (int nj = 0; nj < 8; ++nj) {
                cO[nj][2 * h + 0] *= alpha;
                cO[nj][2 * h + 1] *= alpha;
            }
        }

        // ---- O += P Vh; l += P * ones ----
        float cL[4] = {0.f, 0.f, 0.f, 0.f};
        const uint32_t vbh = stb + 9216 + frow;
#pragma unroll
        for (int ks = 0; ks < 4; ++ks) {
            uint32_t aP[4] = {pH[0][2 * ks], pH[1][2 * ks],
                              pH[0][2 * ks + 1], pH[1][2 * ks + 1]};
            mma16816(cL, aP, onesb);
#pragma unroll
            for (int njp = 0; njp < 4; ++njp) {
                uint32_t v0, v1, v2, v3;
                LDSM4(v0, v1, v2, v3, vbh + njp * 2304 + ks * 32);
                uint32_t vA[2] = {v0, v1}, vB[2] = {v2, v3};
                mma16816(cO[2 * njp], aP, vA);
                mma16816(cO[2 * njp + 1], aP, vB);
            }
        }
        lrow[0] += cL[0];
        lrow[1] += cL[2];
    }

    // ---- epilogue: normalize, split to fp16 hi/lo for proj GEMM ----
    const float i0 = 1.f / lrow[0];
    const float i1 = 1.f / lrow[1];
    const int q0 = qbase + wid * 16 + g;
    const int b = bh >> 4, hh = bh & 15;
    const size_t o0 = (size_t)(b * T_ + q0) * D_ + hh * 64 + 2 * t;
    const size_t o1 = o0 + (size_t)8 * D_;
#pragma unroll
    for (int nj = 0; nj < 8; ++nj) {
        uint32_t hi, lo;
        split2h(cO[nj][0] * i0, cO[nj][1] * i0, hi, lo);
        *(uint32_t*)(g_Oh + o0 + nj * 8) = hi;
        *(uint32_t*)(g_Ol + o0 + nj * 8) = lo;
        split2h(cO[nj][2] * i1, cO[nj][3] * i1, hi, lo);
        *(uint32_t*)(g_Oh + o1 + nj * 8) = hi;
        *(uint32_t*)(g_Ol + o1 + nj * 8) = lo;
    }
}

// =====================================================================
extern "C" void kernel_launch(void* const* d_in, const int* in_sizes, int n_in,
                              void* d_out, int out_size)
{
    const float* x     = (const float*)d_in[0];
    const float* Wqkv  = (const float*)d_in[1];
    const float* Wproj = (const float*)d_in[2];
    const float* bproj = (const float*)d_in[3];
    float* out = (float*)d_out;
    (void)in_sizes; (void)n_in; (void)out_size;

    cudaFuncSetAttribute(gemm_mma<0>, cudaFuncAttributeMaxDynamicSharedMemorySize, G_SMEM);
    cudaFuncSetAttribute(gemm_mma<1>, cudaFuncAttributeMaxDynamicSharedMemorySize, G_SMEM);
    cudaFuncSetAttribute(flash_mma,   cudaFuncAttributeMaxDynamicSharedMemorySize, FA_SMEM);

    convert_in<<<(unsigned)((CX + CQ + CP) / 256), 256>>>(x, Wqkv, Wproj);

    dim3 gq(N_QKV / 128, M1 / 128);   // 24 x 64
    gemm_mma<0><<<gq, 256, G_SMEM>>>(nullptr, nullptr);

    dim3 gt(T_ / 64, B_ * H_);        // 32 x 64
    transpose_v<<<gt, 256>>>();

    dim3 ga(T_ / 64, B_ * H_);        // 32 x 64
    flash_mma<<<ga, 128, FA_SMEM>>>();

    dim3 gp(D_ / 128, M1 / 128);      // 8 x 64
    gemm_mma<1><<<gp, 256, G_SMEM>>>(bproj, out);
}

// round 11
// speedup vs baseline: 5.8378x; 1.1269x over previous
#include <cuda_runtime.h>
#include <cuda_fp16.h>
#include <cstdint>

#define DEVINLINE __device__ __forceinline__

constexpr int B_  = 4;
constexpr int T_  = 2048;
constexpr int D_  = 1024;
constexpr int H_  = 16;
constexpr int HD_ = 64;
constexpr int M1  = B_ * T_;              // 8192
constexpr int N_QKV = 3 * D_;             // 3072
constexpr size_t NE = (size_t)M1 * D_;    // 8388608

// ---- scratch (static __device__; no allocation allowed) ----
__device__ __half g_xh[NE], g_xl[NE];
__device__ __half g_wqh[(size_t)N_QKV * D_];
__device__ __half g_wph[(size_t)D_ * D_];
__device__ __half g_Qh[NE], g_Kh[NE];
__device__ __half g_Vth[NE];
__device__ __half g_Oh[NE];

// =====================================================================
// helpers (arch-portable PTX only: mma.sync/ldmatrix/cp.async)
// =====================================================================
DEVINLINE uint32_t smem_u32(const void* p) {
    uint32_t a;
    asm("{ .reg .u64 t; cvta.to.shared.u64 t, %1; cvt.u32.u64 %0, t; }" : "=r"(a) : "l"(p));
    return a;
}
DEVINLINE float ex2f(float x) {
    float y; asm("ex2.approx.ftz.f32 %0, %1;" : "=f"(y) : "f"(x)); return y;
}
DEVINLINE uint32_t pack2h(float x, float y) {
    __half2 h = __floats2half2_rn(x, y);
    return *reinterpret_cast<uint32_t*>(&h);
}
DEVINLINE void split2h(float x, float y, uint32_t& hi, uint32_t& lo) {
    __half hx = __float2half_rn(x), hy = __float2half_rn(y);
    hi = ((uint32_t)__half_as_ushort(hy) << 16) | (uint32_t)__half_as_ushort(hx);
    lo = pack2h(x - __half2float(hx), y - __half2float(hy));
}
DEVINLINE void mma16816(float c[4], const uint32_t a[4], const uint32_t b[2]) {
    asm volatile(
        "mma.sync.aligned.m16n8k16.row.col.f32.f16.f16.f32 "
        "{%0,%1,%2,%3}, {%4,%5,%6,%7}, {%8,%9}, {%0,%1,%2,%3};"
        : "+f"(c[0]), "+f"(c[1]), "+f"(c[2]), "+f"(c[3])
        : "r"(a[0]), "r"(a[1]), "r"(a[2]), "r"(a[3]), "r"(b[0]), "r"(b[1]));
}
#define LDSM4(r0, r1, r2, r3, addr)                                           \
    asm volatile("ldmatrix.sync.aligned.m8n8.x4.shared.b16 {%0,%1,%2,%3}, [%4];" \
        : "=r"(r0), "=r"(r1), "=r"(r2), "=r"(r3) : "r"(addr))
DEVINLINE void ldsm4a(uint32_t r[4], uint32_t addr) { LDSM4(r[0], r[1], r[2], r[3], addr); }
DEVINLINE void cp16(uint32_t dst, const void* src) {
    asm volatile("cp.async.cg.shared.global [%0], [%1], 16;" :: "r"(dst), "l"(src));
}
#define CP_COMMIT() asm volatile("cp.async.commit_group;" ::: "memory")
#define CP_WAIT0()  asm volatile("cp.async.wait_group 0;" ::: "memory")
#define CP_WAIT2()  asm volatile("cp.async.wait_group 2;" ::: "memory")

// =====================================================================
// convert inputs: x -> (hi,lo) fp16; W_qkv, W_proj -> hi fp16
// =====================================================================
constexpr size_t CX = NE / 4;
constexpr size_t CQ = (size_t)N_QKV * D_ / 4;
constexpr size_t CP = (size_t)D_ * D_ / 4;
__global__ void convert_in(const float* __restrict__ x, const float* __restrict__ wq,
                           const float* __restrict__ wp)
{
    size_t i = (size_t)blockIdx.x * 256 + threadIdx.x;
    if (i < CX) {
        float4 v = ((const float4*)x)[i];
        uint32_t h0, l0, h1, l1;
        split2h(v.x, v.y, h0, l0);
        split2h(v.z, v.w, h1, l1);
        ((uint2*)g_xh)[i] = make_uint2(h0, h1);
        ((uint2*)g_xl)[i] = make_uint2(l0, l1);
    } else if (i < CX + CQ) {
        size_t j = i - CX;
        float4 v = ((const float4*)wq)[j];
        ((uint2*)g_wqh)[j] = make_uint2(pack2h(v.x, v.y), pack2h(v.z, v.w));
    } else {
        size_t j = i - CX - CQ;
        float4 v = ((const float4*)wp)[j];
        ((uint2*)g_wph)[j] = make_uint2(pack2h(v.x, v.y), pack2h(v.z, v.w));
    }
}

// =====================================================================
// HMMA GEMM. Tile 128x128x16, 8 warps, cp.async 4-stage, ldmatrix.
// MODE 0: Q/K blocks (bx<16) 1-term xh*Wh; V blocks (bx>=16) 2-term.
//         Q pre-scaled -> g_Qh; K -> g_Kh; V -> g_Vth TRANSPOSED fp16.
// MODE 1: 1-term Oh*Wph + bias -> out.
// =====================================================================
constexpr int STG_B = 18432;
constexpr int G_SMEM = 4 * STG_B;
constexpr float SC_Q = 0.18033688011112042385f;   // log2(e)/sqrt(64)

template <int MODE>
__global__ __launch_bounds__(256, 2)
void gemm_mma(const float* __restrict__ bias, float* __restrict__ Cout)
{
    extern __shared__ __align__(16) char smg[];
    const uint32_t sb = smem_u32(smg);
    const __half* Ah = (MODE == 0) ? g_xh : g_Oh;
    const __half* Al = g_xl;
    const __half* Bh = (MODE == 0) ? g_wqh : g_wph;
    const bool two = (MODE == 0) && (blockIdx.x >= 16);

    const int tid = threadIdx.x, lane = tid & 31, wid = tid >> 5;
    const int g = lane >> 2, t = lane & 3;
    const int wm = wid >> 1, wn = wid & 1;
    const int bm = blockIdx.y * 128, bn = blockIdx.x * 128;

    float c[2][8][4];
#pragma unroll
    for (int i = 0; i < 2; ++i)
#pragma unroll
        for (int j = 0; j < 8; ++j)
#pragma unroll
            for (int k = 0; k < 4; ++k) c[i][j][k] = 0.f;

    const int ldrow = tid >> 1, ldh = (tid & 1) * 8;
    auto issue = [&](int s, int kt) {
        const uint32_t dst = sb + s * STG_B + ldrow * 48 + ldh * 2;
        const int k0 = kt * 16 + ldh;
        cp16(dst,         Ah + (size_t)(bm + ldrow) * D_ + k0);
        if (two) cp16(dst + 6144, Al + (size_t)(bm + ldrow) * D_ + k0);
        cp16(dst + 12288, Bh + (size_t)(bn + ldrow) * D_ + k0);
    };

    const uint32_t aoff = (uint32_t)((wm * 32 + (lane & 7) + (lane & 8)) * 48 + (lane >> 4) * 16);
    const uint32_t boff = (uint32_t)(12288 + (wn * 64 + (lane & 7) + ((lane >> 1) & 8)) * 48 + (lane & 8) * 2);

#pragma unroll 1
    for (int s = 0; s < 3; ++s) { issue(s, s); CP_COMMIT(); }

    constexpr int NT = D_ / 16;
    for (int kt = 0; kt < NT; ++kt) {
        CP_WAIT2();
        __syncthreads();
        if (kt + 3 < NT) issue((kt + 3) & 3, kt + 3);
        CP_COMMIT();

        const uint32_t stb = sb + (kt & 3) * STG_B;
        uint32_t ah[2][4], al[2][4];
        ldsm4a(ah[0], stb + aoff);
        ldsm4a(ah[1], stb + aoff + 768);
        if (two) {
            ldsm4a(al[0], stb + aoff + 6144);
            ldsm4a(al[1], stb + aoff + 6912);
        }
#pragma unroll
        for (int njp = 0; njp < 4; ++njp) {
            uint32_t b0, b1, b2, b3;
            LDSM4(b0, b1, b2, b3, stb + boff + njp * 768);
            uint32_t bA[2] = {b0, b1}, bB[2] = {b2, b3};
            mma16816(c[0][2 * njp], ah[0], bA);
            mma16816(c[1][2 * njp], ah[1], bA);
            mma16816(c[0][2 * njp + 1], ah[0], bB);
            mma16816(c[1][2 * njp + 1], ah[1], bB);
            if (two) {
                mma16816(c[0][2 * njp], al[0], bA);
                mma16816(c[1][2 * njp], al[1], bA);
                mma16816(c[0][2 * njp + 1], al[0], bB);
                mma16816(c[1][2 * njp + 1], al[1], bB);
            }
        }
    }

    // epilogue
#pragma unroll
    for (int mi = 0; mi < 2; ++mi) {
        const int r0 = bm + wm * 32 + mi * 16 + g;
        const int r1 = r0 + 8;
#pragma unroll
        for (int nj = 0; nj < 8; ++nj) {
            const int cn = bn + wn * 64 + nj * 8 + 2 * t;
            if (MODE == 0) {
                const int part = cn >> 10, hh = (cn >> 6) & 15, dd = cn & 63;
                const int bb = r0 >> 11;                // r0, r1 share the 2048-block
                const int tt0 = r0 & 2047, tt1 = r1 & 2047;
                if (part == 2) {
                    // direct transposed V: g_Vth[((bb*H+hh)*HD + dd)*T + t]
                    const size_t vb = ((size_t)((bb * H_ + hh) * HD_) + dd) * T_;
                    g_Vth[vb + tt0]      = __float2half_rn(c[mi][nj][0]);
                    g_Vth[vb + T_ + tt0] = __float2half_rn(c[mi][nj][1]);
                    g_Vth[vb + tt1]      = __float2half_rn(c[mi][nj][2]);
                    g_Vth[vb + T_ + tt1] = __float2half_rn(c[mi][nj][3]);
                } else {
                    const size_t o0 = (((size_t)(bb * H_ + hh) * T_ + tt0) << 6) + dd;
                    const size_t o1 = (((size_t)(bb * H_ + hh) * T_ + tt1) << 6) + dd;
                    if (part == 0) {
                        *(uint32_t*)(g_Qh + o0) = pack2h(c[mi][nj][0] * SC_Q, c[mi][nj][1] * SC_Q);
                        *(uint32_t*)(g_Qh + o1) = pack2h(c[mi][nj][2] * SC_Q, c[mi][nj][3] * SC_Q);
                    } else {
                        *(uint32_t*)(g_Kh + o0) = pack2h(c[mi][nj][0], c[mi][nj][1]);
                        *(uint32_t*)(g_Kh + o1) = pack2h(c[mi][nj][2], c[mi][nj][3]);
                    }
                }
            } else {
                float2 bv = *(const float2*)&bias[cn];
                *(float2*)&Cout[(size_t)r0 * D_ + cn] =
                    make_float2(c[mi][nj][0] + bv.x, c[mi][nj][1] + bv.y);
                *(float2*)&Cout[(size_t)r1 * D_ + cn] =
                    make_float2(c[mi][nj][2] + bv.x, c[mi][nj][3] + bv.y);
            }
        }
    }
}

// =====================================================================
// HMMA flash attention, causal. q-tile 64, 4 warps, LPT order.
// QK 1-term Qh*Kh (Q pre-scaled, log2 units); P fp16; PV 1-term Ph*Vh;
// row-sum l via all-ones MMA column.  O written fp16 (1-term proj).
// smem: 2 KV stages of [Kh|Vth], 64 rows x 144B each.
// =====================================================================
constexpr int KSTG = 2 * 64 * 144;        // 18432
constexpr int FA_SMEM = 2 * KSTG;         // 36864

__global__ __launch_bounds__(128, 3)
void flash_mma()
{
    extern __shared__ __align__(16) char sma[];
    const uint32_t sb = smem_u32(sma);
    const int tid = threadIdx.x, lane = tid & 31, wid = tid >> 5;
    const int g = lane >> 2, t = lane & 3;
    const int qt = gridDim.x - 1 - blockIdx.x;   // LPT: longest CTAs first
    const int bh = blockIdx.y;
    const int qbase = qt * 64;
    const int nkt = qt + 1;

    const size_t hb = (size_t)bh * T_ * HD_;
    const __half* Qhp = g_Qh + hb;
    const __half* Khp = g_Kh + hb;
    const __half* Vhp = g_Vth + hb;

    const float NEG_INF = __int_as_float(0xff800000);

    // ---- stage Q, hoist fragments ----
#pragma unroll
    for (int u = 0; u < 4; ++u) {
        int cidx = u * 128 + tid;
        int row = (cidx >> 3) & 63, ch = cidx & 7;
        cp16(sb + row * 144 + ch * 16, Qhp + (size_t)(qbase + row) * HD_ + ch * 8);
    }
    CP_COMMIT(); CP_WAIT0(); __syncthreads();

    uint32_t qh[4][4];
    {
        const uint32_t qb = sb + (wid * 16 + (lane & 7) + (lane & 8)) * 144 + (lane >> 4) * 16;
#pragma unroll
        for (int ks = 0; ks < 4; ++ks) ldsm4a(qh[ks], qb + ks * 32);
    }
    __syncthreads();

    auto issueKV = [&](int s, int kt) {
        const int ktb = kt * 64;
#pragma unroll
        for (int u = 0; u < 8; ++u) {
            int cidx = u * 128 + tid;
            int arr = cidx >> 9, row = (cidx >> 3) & 63, ch = cidx & 7;
            uint32_t dst = sb + s * KSTG + arr * 9216 + row * 144 + ch * 16;
            const __half* src = (arr == 0)
                ? Khp + (size_t)(ktb + row) * HD_ + ch * 8
                : Vhp + (size_t)row * T_ + ktb + ch * 8;
            cp16(dst, src);
        }
    };

    float cO[8][4];
#pragma unroll
    for (int j = 0; j < 8; ++j)
#pragma unroll
        for (int k = 0; k < 4; ++k) cO[j][k] = 0.f;
    float mrow[2] = {NEG_INF, NEG_INF};
    float lrow[2] = {0.f, 0.f};

    issueKV(0, 0); CP_COMMIT();

    const uint32_t frow = (uint32_t)(((lane & 7) + ((lane >> 1) & 8)) * 144 + (lane & 8) * 2);
    const uint32_t ones2 = 0x3C003C00u;
    const uint32_t onesb[2] = {ones2, ones2};

    for (int kt = 0; kt < nkt; ++kt) {
        CP_WAIT0();
        __syncthreads();
        if (kt + 1 < nkt) issueKV((kt + 1) & 1, kt + 1);
        CP_COMMIT();

        const uint32_t stb = sb + (kt & 1) * KSTG;

        // ---- S = Q K^T (1-term; log2 units) ----
        float cS[8][4];
#pragma unroll
        for (int j = 0; j < 8; ++j)
#pragma unroll
            for (int k = 0; k < 4; ++k) cS[j][k] = 0.f;

        const uint32_t kb = stb + frow;
#pragma unroll
        for (int ks = 0; ks < 4; ++ks) {
#pragma unroll
            for (int njp = 0; njp < 4; ++njp) {
                uint32_t b0, b1, b2, b3;
                LDSM4(b0, b1, b2, b3, kb + njp * 2304 + ks * 32);
                uint32_t bA[2] = {b0, b1}, bB[2] = {b2, b3};
                mma16816(cS[2 * njp], qh[ks], bA);
                mma16816(cS[2 * njp + 1], qh[ks], bB);
            }
        }

        // ---- causal mask (diagonal tile only) ----
        if (kt == nkt - 1) {
            const int kb0 = kt * 64;
#pragma unroll
            for (int h = 0; h < 2; ++h) {
                const int qrow = qbase + wid * 16 + g + 8 * h;
#pragma unroll
                for (int nj = 0; nj < 8; ++nj)
#pragma unroll
                    for (int cc = 0; cc < 2; ++cc)
                        if (kb0 + nj * 8 + 2 * t + cc > qrow) cS[nj][2 * h + cc] = NEG_INF;
            }
        }

        // ---- online softmax: f32 EX2, pack to fp16 P ----
        uint32_t pH[2][8];
#pragma unroll
        for (int h = 0; h < 2; ++h) {
            float mloc = NEG_INF;
#pragma unroll
            for (int nj = 0; nj < 8; ++nj)
                mloc = fmaxf(mloc, fmaxf(cS[nj][2 * h], cS[nj][2 * h + 1]));
            mloc = fmaxf(mloc, __shfl_xor_sync(0xffffffffu, mloc, 1));
            mloc = fmaxf(mloc, __shfl_xor_sync(0xffffffffu, mloc, 2));
            const float mnew  = fmaxf(mrow[h], mloc);
            const float alpha = ex2f(mrow[h] - mnew);
            mrow[h] = mnew;
#pragma unroll
            for (int nj = 0; nj < 8; ++nj) {
                float p0 = ex2f(cS[nj][2 * h]     - mnew);
                float p1 = ex2f(cS[nj][2 * h + 1] - mnew);
                pH[h][nj] = pack2h(p0, p1);
            }
            lrow[h] *= alpha;
#pragma unroll
            for (int nj = 0; nj < 8; ++nj) {
                cO[nj][2 * h + 0] *= alpha;
                cO[nj][2 * h + 1] *= alpha;
            }
        }

        // ---- O += P Vh; l += P * ones ----
        float cL[4] = {0.f, 0.f, 0.f, 0.f};
        const uint32_t vbh = stb + 9216 + frow;
#pragma unroll
        for (int ks = 0; ks < 4; ++ks) {
            uint32_t aP[4] = {pH[0][2 * ks], pH[1][2 * ks],
                              pH[0][2 * ks + 1], pH[1][2 * ks + 1]};
            mma16816(cL, aP, onesb);
#pragma unroll
            for (int njp = 0; njp < 4; ++njp) {
                uint32_t v0, v1, v2, v3;
                LDSM4(v0, v1, v2, v3, vbh + njp * 2304 + ks * 32);
                uint32_t vA[2] = {v0, v1}, vB[2] = {v2, v3};
                mma16816(cO[2 * njp], aP, vA);
                mma16816(cO[2 * njp + 1], aP, vB);
            }
        }
        lrow[0] += cL[0];
        lrow[1] += cL[2];
    }

    // ---- epilogue: normalize, fp16 O for 1-term proj ----
    const float i0 = 1.f / lrow[0];
    const float i1 = 1.f / lrow[1];
    const int q0 = qbase + wid * 16 + g;
    const int b = bh >> 4, hh = bh & 15;
    const size_t o0 = (size_t)(b * T_ + q0) * D_ + hh * 64 + 2 * t;
    const size_t o1 = o0 + (size_t)8 * D_;
#pragma unroll
    for (int nj = 0; nj < 8; ++nj) {
        *(uint32_t*)(g_Oh + o0 + nj * 8) = pack2h(cO[nj][0] * i0, cO[nj][1] * i0);
        *(uint32_t*)(g_Oh + o1 + nj * 8) = pack2h(cO[nj][2] * i1, cO[nj][3] * i1);
    }
}

// =====================================================================
extern "C" void kernel_launch(void* const* d_in, const int* in_sizes, int n_in,
                              void* d_out, int out_size)
{
    const float* x     = (const float*)d_in[0];
    const float* Wqkv  = (const float*)d_in[1];
    const float* Wproj = (const float*)d_in[2];
    const float* bproj = (const float*)d_in[3];
    float* out = (float*)d_out;
    (void)in_sizes; (void)n_in; (void)out_size;

    cudaFuncSetAttribute(gemm_mma<0>, cudaFuncAttributeMaxDynamicSharedMemorySize, G_SMEM);
    cudaFuncSetAttribute(gemm_mma<1>, cudaFuncAttributeMaxDynamicSharedMemorySize, G_SMEM);
    cudaFuncSetAttribute(flash_mma,   cudaFuncAttributeMaxDynamicSharedMemorySize, FA_SMEM);

    convert_in<<<(unsigned)((CX + CQ + CP) / 256), 256>>>(x, Wqkv, Wproj);

    dim3 gq(N_QKV / 128, M1 / 128);   // 24 x 64
    gemm_mma<0><<<gq, 256, G_SMEM>>>(nullptr, nullptr);

    dim3 ga(T_ / 64, B_ * H_);        // 32 x 64
    flash_mma<<<ga, 128, FA_SMEM>>>();

    dim3 gp(D_ / 128, M1 / 128);      // 8 x 64
    gemm_mma<1><<<gp, 256, G_SMEM>>>(bproj, out);
}

// round 12
// speedup vs baseline: 6.2020x; 1.0624x over previous
#include <cuda_runtime.h>
#include <cuda_fp16.h>
#include <cstdint>

#define DEVINLINE __device__ __forceinline__

constexpr int B_  = 4;
constexpr int T_  = 2048;
constexpr int D_  = 1024;
constexpr int H_  = 16;
constexpr int HD_ = 64;
constexpr int M1  = B_ * T_;              // 8192
constexpr int N_QKV = 3 * D_;             // 3072
constexpr size_t NE = (size_t)M1 * D_;    // 8388608

// ---- scratch (static __device__; no allocation allowed) ----
__device__ __half g_xh[NE];
__device__ __half g_wqh[(size_t)N_QKV * D_];
__device__ __half g_wph[(size_t)D_ * D_];
__device__ __half g_Qh[NE], g_Kh[NE];
__device__ __half g_Vth[NE];
__device__ __half g_Oh[NE];

// =====================================================================
// helpers (arch-portable PTX only: mma.sync/ldmatrix/cp.async)
// =====================================================================
DEVINLINE uint32_t smem_u32(const void* p) {
    uint32_t a;
    asm("{ .reg .u64 t; cvta.to.shared.u64 t, %1; cvt.u32.u64 %0, t; }" : "=r"(a) : "l"(p));
    return a;
}
DEVINLINE float ex2f(float x) {
    float y; asm("ex2.approx.ftz.f32 %0, %1;" : "=f"(y) : "f"(x)); return y;
}
DEVINLINE uint32_t pack2h(float x, float y) {
    __half2 h = __floats2half2_rn(x, y);
    return *reinterpret_cast<uint32_t*>(&h);
}
DEVINLINE void mma16816(float c[4], const uint32_t a[4], const uint32_t b[2]) {
    asm volatile(
        "mma.sync.aligned.m16n8k16.row.col.f32.f16.f16.f32 "
        "{%0,%1,%2,%3}, {%4,%5,%6,%7}, {%8,%9}, {%0,%1,%2,%3};"
        : "+f"(c[0]), "+f"(c[1]), "+f"(c[2]), "+f"(c[3])
        : "r"(a[0]), "r"(a[1]), "r"(a[2]), "r"(a[3]), "r"(b[0]), "r"(b[1]));
}
#define LDSM4(r0, r1, r2, r3, addr)                                           \
    asm volatile("ldmatrix.sync.aligned.m8n8.x4.shared.b16 {%0,%1,%2,%3}, [%4];" \
        : "=r"(r0), "=r"(r1), "=r"(r2), "=r"(r3) : "r"(addr))
DEVINLINE void ldsm4a(uint32_t r[4], uint32_t addr) { LDSM4(r[0], r[1], r[2], r[3], addr); }
DEVINLINE void cp16(uint32_t dst, const void* src) {
    asm volatile("cp.async.cg.shared.global [%0], [%1], 16;" :: "r"(dst), "l"(src));
}
#define CP_COMMIT() asm volatile("cp.async.commit_group;" ::: "memory")
#define CP_WAIT0()  asm volatile("cp.async.wait_group 0;" ::: "memory")
#define CP_WAIT1()  asm volatile("cp.async.wait_group 1;" ::: "memory")

// =====================================================================
// convert inputs: x -> hi fp16; W_qkv, W_proj -> hi fp16
// =====================================================================
constexpr size_t CX = NE / 4;
constexpr size_t CQ = (size_t)N_QKV * D_ / 4;
constexpr size_t CP = (size_t)D_ * D_ / 4;
__global__ void convert_in(const float* __restrict__ x, const float* __restrict__ wq,
                           const float* __restrict__ wp)
{
    size_t i = (size_t)blockIdx.x * 256 + threadIdx.x;
    if (i < CX) {
        float4 v = ((const float4*)x)[i];
        ((uint2*)g_xh)[i] = make_uint2(pack2h(v.x, v.y), pack2h(v.z, v.w));
    } else if (i < CX + CQ) {
        size_t j = i - CX;
        float4 v = ((const float4*)wq)[j];
        ((uint2*)g_wqh)[j] = make_uint2(pack2h(v.x, v.y), pack2h(v.z, v.w));
    } else {
        size_t j = i - CX - CQ;
        float4 v = ((const float4*)wp)[j];
        ((uint2*)g_wph)[j] = make_uint2(pack2h(v.x, v.y), pack2h(v.z, v.w));
    }
}

// =====================================================================
// HMMA GEMM, 1-term. CTA tile 128(M)x256(N), 8 warps (warp 64x64, 2m x 4n),
// K-stage 32, 3-stage cp.async, ldmatrix. Rows 80B (64B data + 16 pad).
// MODE 0: x*Wqkv -> Q (pre-scaled) / K / V(transposed), all fp16.
// MODE 1: Oh*Wproj + bias -> out (f32).
// =====================================================================
constexpr int GRS   = 80;                  // smem row stride bytes
constexpr int ASTG  = 128 * GRS;           // 10240
constexpr int BSTG  = 256 * GRS;           // 20480
constexpr int STG_B = ASTG + BSTG;         // 30720
constexpr int G_SMEM = 3 * STG_B;          // 92160
constexpr float SC_Q = 0.18033688011112042385f;   // log2(e)/sqrt(64)

template <int MODE>
__global__ __launch_bounds__(256)
void gemm_mma(const float* __restrict__ bias, float* __restrict__ Cout)
{
    extern __shared__ __align__(16) char smg[];
    const uint32_t sb = smem_u32(smg);
    const __half* Ah = (MODE == 0) ? g_xh : g_Oh;
    const __half* Bh = (MODE == 0) ? g_wqh : g_wph;

    const int tid = threadIdx.x, lane = tid & 31, wid = tid >> 5;
    const int g = lane >> 2, t = lane & 3;
    const int wm = wid & 1, wn = wid >> 1;
    const int bm = blockIdx.y * 128, bn = blockIdx.x * 256;

    float c[4][8][4];
#pragma unroll
    for (int i = 0; i < 4; ++i)
#pragma unroll
        for (int j = 0; j < 8; ++j)
#pragma unroll
            for (int k = 0; k < 4; ++k) c[i][j][k] = 0.f;

    auto issue = [&](int s, int kt) {
        const uint32_t st = sb + s * STG_B;
        const int k0 = kt * 32;
#pragma unroll
        for (int u = 0; u < 6; ++u) {
            int idx = u * 256 + tid;
            if (idx < 512) {
                int row = idx >> 2, ch = idx & 3;
                cp16(st + row * GRS + ch * 16,
                     Ah + (size_t)(bm + row) * D_ + k0 + ch * 8);
            } else {
                int j = idx - 512;
                int row = j >> 2, ch = j & 3;
                cp16(st + ASTG + row * GRS + ch * 16,
                     Bh + (size_t)(bn + row) * D_ + k0 + ch * 8);
            }
        }
    };

    const uint32_t abase = (uint32_t)((wm * 64 + (lane & 7) + (lane & 8)) * GRS + (lane >> 4) * 16);
    const uint32_t bbase = (uint32_t)(ASTG + (wn * 64 + (lane & 7) + ((lane >> 1) & 8)) * GRS + (lane & 8) * 2);

    issue(0, 0); CP_COMMIT();
    issue(1, 1); CP_COMMIT();

    constexpr int NT = D_ / 32;   // 32
    for (int kt = 0; kt < NT; ++kt) {
        CP_WAIT1();
        __syncthreads();
        if (kt + 2 < NT) issue((kt + 2) % 3, kt + 2);
        CP_COMMIT();

        const uint32_t stb = sb + (kt % 3) * STG_B;
#pragma unroll
        for (int ks = 0; ks < 2; ++ks) {
            uint32_t ah[4][4];
#pragma unroll
            for (int mi = 0; mi < 4; ++mi)
                ldsm4a(ah[mi], stb + abase + mi * (16 * GRS) + ks * 32);
#pragma unroll
            for (int njp = 0; njp < 4; ++njp) {
                uint32_t b0, b1, b2, b3;
                LDSM4(b0, b1, b2, b3, stb + bbase + njp * (16 * GRS) + ks * 32);
                uint32_t bA[2] = {b0, b1}, bB[2] = {b2, b3};
#pragma unroll
                for (int mi = 0; mi < 4; ++mi) {
                    mma16816(c[mi][2 * njp],     ah[mi], bA);
                    mma16816(c[mi][2 * njp + 1], ah[mi], bB);
                }
            }
        }
    }

    // epilogue
#pragma unroll
    for (int mi = 0; mi < 4; ++mi) {
        const int r0 = bm + wm * 64 + mi * 16 + g;
        const int r1 = r0 + 8;
#pragma unroll
        for (int nj = 0; nj < 8; ++nj) {
            const int cn = bn + wn * 64 + nj * 8 + 2 * t;
            if (MODE == 0) {
                const int part = cn >> 10, hh = (cn >> 6) & 15, dd = cn & 63;
                const int bb = r0 >> 11;
                const int tt0 = r0 & 2047, tt1 = r1 & 2047;
                if (part == 2) {
                    const size_t vb = ((size_t)((bb * H_ + hh) * HD_) + dd) * T_;
                    g_Vth[vb + tt0]      = __float2half_rn(c[mi][nj][0]);
                    g_Vth[vb + T_ + tt0] = __float2half_rn(c[mi][nj][1]);
                    g_Vth[vb + tt1]      = __float2half_rn(c[mi][nj][2]);
                    g_Vth[vb + T_ + tt1] = __float2half_rn(c[mi][nj][3]);
                } else {
                    const size_t o0 = (((size_t)(bb * H_ + hh) * T_ + tt0) << 6) + dd;
                    const size_t o1 = (((size_t)(bb * H_ + hh) * T_ + tt1) << 6) + dd;
                    if (part == 0) {
                        *(uint32_t*)(g_Qh + o0) = pack2h(c[mi][nj][0] * SC_Q, c[mi][nj][1] * SC_Q);
                        *(uint32_t*)(g_Qh + o1) = pack2h(c[mi][nj][2] * SC_Q, c[mi][nj][3] * SC_Q);
                    } else {
                        *(uint32_t*)(g_Kh + o0) = pack2h(c[mi][nj][0], c[mi][nj][1]);
                        *(uint32_t*)(g_Kh + o1) = pack2h(c[mi][nj][2], c[mi][nj][3]);
                    }
                }
            } else {
                float2 bv = *(const float2*)&bias[cn];
                *(float2*)&Cout[(size_t)r0 * D_ + cn] =
                    make_float2(c[mi][nj][0] + bv.x, c[mi][nj][1] + bv.y);
                *(float2*)&Cout[(size_t)r1 * D_ + cn] =
                    make_float2(c[mi][nj][2] + bv.x, c[mi][nj][3] + bv.y);
            }
        }
    }
}

// =====================================================================
// HMMA flash attention, causal. q-tile 64, 4 warps, LPT order.
// QK 1-term Qh*Kh (Q pre-scaled, log2 units); P fp16; PV 1-term Ph*Vh;
// row-sum l via all-ones MMA column.  O written fp16 (1-term proj).
// smem: 2 KV stages of [Kh|Vth], 64 rows x 144B each.
// =====================================================================
constexpr int KSTG = 2 * 64 * 144;        // 18432
constexpr int FA_SMEM = 2 * KSTG;         // 36864

__global__ __launch_bounds__(128, 3)
void flash_mma()
{
    extern __shared__ __align__(16) char sma[];
    const uint32_t sb = smem_u32(sma);
    const int tid = threadIdx.x, lane = tid & 31, wid = tid >> 5;
    const int g = lane >> 2, t = lane & 3;
    const int qt = gridDim.x - 1 - blockIdx.x;   // LPT: longest CTAs first
    const int bh = blockIdx.y;
    const int qbase = qt * 64;
    const int nkt = qt + 1;

    const size_t hb = (size_t)bh * T_ * HD_;
    const __half* Qhp = g_Qh + hb;
    const __half* Khp = g_Kh + hb;
    const __half* Vhp = g_Vth + hb;

    const float NEG_INF = __int_as_float(0xff800000);

    // ---- stage Q, hoist fragments ----
#pragma unroll
    for (int u = 0; u < 4; ++u) {
        int cidx = u * 128 + tid;
        int row = (cidx >> 3) & 63, ch = cidx & 7;
        cp16(sb + row * 144 + ch * 16, Qhp + (size_t)(qbase + row) * HD_ + ch * 8);
    }
    CP_COMMIT(); CP_WAIT0(); __syncthreads();

    uint32_t qh[4][4];
    {
        const uint32_t qb = sb + (wid * 16 + (lane & 7) + (lane & 8)) * 144 + (lane >> 4) * 16;
#pragma unroll
        for (int ks = 0; ks < 4; ++ks) ldsm4a(qh[ks], qb + ks * 32);
    }
    __syncthreads();

    auto issueKV = [&](int s, int kt) {
        const int ktb = kt * 64;
#pragma unroll
        for (int u = 0; u < 8; ++u) {
            int cidx = u * 128 + tid;
            int arr = cidx >> 9, row = (cidx >> 3) & 63, ch = cidx & 7;
            uint32_t dst = sb + s * KSTG + arr * 9216 + row * 144 + ch * 16;
            const __half* src = (arr == 0)
                ? Khp + (size_t)(ktb + row) * HD_ + ch * 8
                : Vhp + (size_t)row * T_ + ktb + ch * 8;
            cp16(dst, src);
        }
    };

    float cO[8][4];
#pragma unroll
    for (int j = 0; j < 8; ++j)
#pragma unroll
        for (int k = 0; k < 4; ++k) cO[j][k] = 0.f;
    float mrow[2] = {NEG_INF, NEG_INF};
    float lrow[2] = {0.f, 0.f};

    issueKV(0, 0); CP_COMMIT();

    const uint32_t frow = (uint32_t)(((lane & 7) + ((lane >> 1) & 8)) * 144 + (lane & 8) * 2);
    const uint32_t ones2 = 0x3C003C00u;
    const uint32_t onesb[2] = {ones2, ones2};

    for (int kt = 0; kt < nkt; ++kt) {
        CP_WAIT0();
        __syncthreads();
        if (kt + 1 < nkt) issueKV((kt + 1) & 1, kt + 1);
        CP_COMMIT();

        const uint32_t stb = sb + (kt & 1) * KSTG;

        // ---- S = Q K^T (1-term; log2 units) ----
        float cS[8][4];
#pragma unroll
        for (int j = 0; j < 8; ++j)
#pragma unroll
            for (int k = 0; k < 4; ++k) cS[j][k] = 0.f;

        const uint32_t kb = stb + frow;
#pragma unroll
        for (int ks = 0; ks < 4; ++ks) {
#pragma unroll
            for (int njp = 0; njp < 4; ++njp) {
                uint32_t b0, b1, b2, b3;
                LDSM4(b0, b1, b2, b3, kb + njp * 2304 + ks * 32);
                uint32_t bA[2] = {b0, b1}, bB[2] = {b2, b3};
                mma16816(cS[2 * njp], qh[ks], bA);
                mma16816(cS[2 * njp + 1], qh[ks], bB);
            }
        }

        // ---- causal mask (diagonal tile only) ----
        if (kt == nkt - 1) {
            const int kb0 = kt * 64;
#pragma unroll
            for (int h = 0; h < 2; ++h) {
                const int qrow = qbase + wid * 16 + g + 8 * h;
#pragma unroll
                for (int nj = 0; nj < 8; ++nj)
#pragma unroll
                    for (int cc = 0; cc < 2; ++cc)
                        if (kb0 + nj * 8 + 2 * t + cc > qrow) cS[nj][2 * h + cc] = NEG_INF;
            }
        }

        // ---- online softmax: f32 EX2, pack to fp16 P ----
        uint32_t pH[2][8];
#pragma unroll
        for (int h = 0; h < 2; ++h) {
            float mloc = NEG_INF;
#pragma unroll
            for (int nj = 0; nj < 8; ++nj)
                mloc = fmaxf(mloc, fmaxf(cS[nj][2 * h], cS[nj][2 * h + 1]));
            mloc = fmaxf(mloc, __shfl_xor_sync(0xffffffffu, mloc, 1));
            mloc = fmaxf(mloc, __shfl_xor_sync(0xffffffffu, mloc, 2));
            const float mnew  = fmaxf(mrow[h], mloc);
            const float alpha = ex2f(mrow[h] - mnew);
            mrow[h] = mnew;
#pragma unroll
            for (int nj = 0; nj < 8; ++nj) {
                float p0 = ex2f(cS[nj][2 * h]     - mnew);
                float p1 = ex2f(cS[nj][2 * h + 1] - mnew);
                pH[h][nj] = pack2h(p0, p1);
            }
            lrow[h] *= alpha;
#pragma unroll
            for (int nj = 0; nj < 8; ++nj) {
                cO[nj][2 * h + 0] *= alpha;
                cO[nj][2 * h + 1] *= alpha;
            }
        }

        // ---- O += P Vh; l += P * ones ----
        float cL[4] = {0.f, 0.f, 0.f, 0.f};
        const uint32_t vbh = stb + 9216 + frow;
#pragma unroll
        for (int ks = 0; ks < 4; ++ks) {
            uint32_t aP[4] = {pH[0][2 * ks], pH[1][2 * ks],
                              pH[0][2 * ks + 1], pH[1][2 * ks + 1]};
            mma16816(cL, aP, onesb);
#pragma unroll
            for (int njp = 0; njp < 4; ++njp) {
                uint32_t v0, v1, v2, v3;
                LDSM4(v0, v1, v2, v3, vbh + njp * 2304 + ks * 32);
                uint32_t vA[2] = {v0, v1}, vB[2] = {v2, v3};
                mma16816(cO[2 * njp], aP, vA);
                mma16816(cO[2 * njp + 1], aP, vB);
            }
        }
        lrow[0] += cL[0];
        lrow[1] += cL[2];
    }

    // ---- epilogue: normalize, fp16 O for 1-term proj ----
    const float i0 = 1.f / lrow[0];
    const float i1 = 1.f / lrow[1];
    const int q0 = qbase + wid * 16 + g;
    const int b = bh >> 4, hh = bh & 15;
    const size_t o0 = (size_t)(b * T_ + q0) * D_ + hh * 64 + 2 * t;
    const size_t o1 = o0 + (size_t)8 * D_;
#pragma unroll
    for (int nj = 0; nj < 8; ++nj) {
        *(uint32_t*)(g_Oh + o0 + nj * 8) = pack2h(cO[nj][0] * i0, cO[nj][1] * i0);
        *(uint32_t*)(g_Oh + o1 + nj * 8) = pack2h(cO[nj][2] * i1, cO[nj][3] * i1);
    }
}

// =====================================================================
extern "C" void kernel_launch(void* const* d_in, const int* in_sizes, int n_in,
                              void* d_out, int out_size)
{
    const float* x     = (const float*)d_in[0];
    const float* Wqkv  = (const float*)d_in[1];
    const float* Wproj = (const float*)d_in[2];
    const float* bproj = (const float*)d_in[3];
    float* out = (float*)d_out;
    (void)in_sizes; (void)n_in; (void)out_size;

    cudaFuncSetAttribute(gemm_mma<0>, cudaFuncAttributeMaxDynamicSharedMemorySize, G_SMEM);
    cudaFuncSetAttribute(gemm_mma<1>, cudaFuncAttributeMaxDynamicSharedMemorySize, G_SMEM);
    cudaFuncSetAttribute(flash_mma,   cudaFuncAttributeMaxDynamicSharedMemorySize, FA_SMEM);

    convert_in<<<(unsigned)((CX + CQ + CP) / 256), 256>>>(x, Wqkv, Wproj);

    dim3 gq(N_QKV / 256, M1 / 128);   // 12 x 64
    gemm_mma<0><<<gq, 256, G_SMEM>>>(nullptr, nullptr);

    dim3 ga(T_ / 64, B_ * H_);        // 32 x 64
    flash_mma<<<ga, 128, FA_SMEM>>>();

    dim3 gp(D_ / 256, M1 / 128);      // 4 x 64
    gemm_mma<1><<<gp, 256, G_SMEM>>>(bproj, out);
}

// round 13
// speedup vs baseline: 6.9440x; 1.1196x over previous
#include <cuda_runtime.h>
#include <cuda_fp16.h>
#include <cstdint>

#define DEVINLINE __device__ __forceinline__

constexpr int B_  = 4;
constexpr int T_  = 2048;
constexpr int D_  = 1024;
constexpr int H_  = 16;
constexpr int HD_ = 64;
constexpr int M1  = B_ * T_;              // 8192
constexpr int N_QKV = 3 * D_;             // 3072
constexpr size_t NE = (size_t)M1 * D_;    // 8388608

// ---- scratch (static __device__; no allocation allowed) ----
__device__ __half g_xh[NE];
__device__ __half g_wqh[(size_t)N_QKV * D_];
__device__ __half g_wph[(size_t)D_ * D_];
__device__ __half g_Qh[NE], g_Kh[NE];
__device__ __half g_Vth[NE];
__device__ __half g_Oh[NE];

// =====================================================================
// helpers (arch-portable PTX only: mma.sync/ldmatrix/cp.async)
// =====================================================================
DEVINLINE uint32_t smem_u32(const void* p) {
    uint32_t a;
    asm("{ .reg .u64 t; cvta.to.shared.u64 t, %1; cvt.u32.u64 %0, t; }" : "=r"(a) : "l"(p));
    return a;
}
DEVINLINE float ex2f(float x) {
    float y; asm("ex2.approx.ftz.f32 %0, %1;" : "=f"(y) : "f"(x)); return y;
}
DEVINLINE uint32_t pack2h(float x, float y) {
    __half2 h = __floats2half2_rn(x, y);
    return *reinterpret_cast<uint32_t*>(&h);
}
DEVINLINE void mma16816(float c[4], const uint32_t a[4], const uint32_t b[2]) {
    asm volatile(
        "mma.sync.aligned.m16n8k16.row.col.f32.f16.f16.f32 "
        "{%0,%1,%2,%3}, {%4,%5,%6,%7}, {%8,%9}, {%0,%1,%2,%3};"
        : "+f"(c[0]), "+f"(c[1]), "+f"(c[2]), "+f"(c[3])
        : "r"(a[0]), "r"(a[1]), "r"(a[2]), "r"(a[3]), "r"(b[0]), "r"(b[1]));
}
#define LDSM4(r0, r1, r2, r3, addr)                                           \
    asm volatile("ldmatrix.sync.aligned.m8n8.x4.shared.b16 {%0,%1,%2,%3}, [%4];" \
        : "=r"(r0), "=r"(r1), "=r"(r2), "=r"(r3) : "r"(addr))
DEVINLINE void ldsm4a(uint32_t r[4], uint32_t addr) { LDSM4(r[0], r[1], r[2], r[3], addr); }
DEVINLINE void cp16(uint32_t dst, const void* src) {
    asm volatile("cp.async.cg.shared.global [%0], [%1], 16;" :: "r"(dst), "l"(src));
}
#define CP_COMMIT() asm volatile("cp.async.commit_group;" ::: "memory")
#define CP_WAIT0()  asm volatile("cp.async.wait_group 0;" ::: "memory")
#define CP_WAIT1()  asm volatile("cp.async.wait_group 1;" ::: "memory")

// =====================================================================
// convert inputs: x -> hi fp16; W_qkv, W_proj -> hi fp16
// =====================================================================
constexpr size_t CX = NE / 4;
constexpr size_t CQ = (size_t)N_QKV * D_ / 4;
constexpr size_t CP = (size_t)D_ * D_ / 4;
__global__ void convert_in(const float* __restrict__ x, const float* __restrict__ wq,
                           const float* __restrict__ wp)
{
    size_t i = (size_t)blockIdx.x * 256 + threadIdx.x;
    if (i < CX) {
        float4 v = ((const float4*)x)[i];
        ((uint2*)g_xh)[i] = make_uint2(pack2h(v.x, v.y), pack2h(v.z, v.w));
    } else if (i < CX + CQ) {
        size_t j = i - CX;
        float4 v = ((const float4*)wq)[j];
        ((uint2*)g_wqh)[j] = make_uint2(pack2h(v.x, v.y), pack2h(v.z, v.w));
    } else {
        size_t j = i - CX - CQ;
        float4 v = ((const float4*)wp)[j];
        ((uint2*)g_wph)[j] = make_uint2(pack2h(v.x, v.y), pack2h(v.z, v.w));
    }
}

// =====================================================================
// HMMA GEMM, 1-term. CTA tile 128(M)x128(N), 4 warps (warp 64x64, 2x2),
// K-stage 32, 3-stage cp.async, ldmatrix, 3 CTAs/SM for overlap.
// MODE 0: x*Wqkv -> Q (pre-scaled) / K / V(transposed), all fp16.
// MODE 1: Oh*Wproj + bias -> out (f32).
// =====================================================================
constexpr int GRS   = 80;                  // smem row stride bytes (64B + 16 pad)
constexpr int ASTG  = 128 * GRS;           // 10240
constexpr int STG_B = 2 * ASTG;            // 20480 (A + B)
constexpr int G_SMEM = 3 * STG_B;          // 61440
constexpr float SC_Q = 0.18033688011112042385f;   // log2(e)/sqrt(64)

template <int MODE>
__global__ __launch_bounds__(128, 3)
void gemm_mma(const float* __restrict__ bias, float* __restrict__ Cout)
{
    extern __shared__ __align__(16) char smg[];
    const uint32_t sb = smem_u32(smg);
    const __half* Ah = (MODE == 0) ? g_xh : g_Oh;
    const __half* Bh = (MODE == 0) ? g_wqh : g_wph;

    const int tid = threadIdx.x, lane = tid & 31, wid = tid >> 5;
    const int g = lane >> 2, t = lane & 3;
    const int wm = wid & 1, wn = wid >> 1;
    const int bm = blockIdx.y * 128, bn = blockIdx.x * 128;

    float c[4][8][4];
#pragma unroll
    for (int i = 0; i < 4; ++i)
#pragma unroll
        for (int j = 0; j < 8; ++j)
#pragma unroll
            for (int k = 0; k < 4; ++k) c[i][j][k] = 0.f;

    auto issue = [&](int s, int kt) {
        const uint32_t st = sb + s * STG_B;
        const int k0 = kt * 32;
#pragma unroll
        for (int u = 0; u < 8; ++u) {
            int idx = u * 128 + tid;                 // 0..1023
            int half = idx >> 9;                     // 0:A rows, 1:B rows
            int row = (idx >> 2) & 127, ch = idx & 3;
            const __half* src = (half ? Bh + (size_t)(bn + row) * D_
                                      : Ah + (size_t)(bm + row) * D_) + k0 + ch * 8;
            cp16(st + half * ASTG + row * GRS + ch * 16, src);
        }
    };

    const uint32_t abase = (uint32_t)((wm * 64 + (lane & 7) + (lane & 8)) * GRS + (lane >> 4) * 16);
    const uint32_t bbase = (uint32_t)(ASTG + (wn * 64 + (lane & 7) + ((lane >> 1) & 8)) * GRS + (lane & 8) * 2);

    issue(0, 0); CP_COMMIT();
    issue(1, 1); CP_COMMIT();

    constexpr int NT = D_ / 32;   // 32
    for (int kt = 0; kt < NT; ++kt) {
        CP_WAIT1();
        __syncthreads();
        if (kt + 2 < NT) issue((kt + 2) % 3, kt + 2);
        CP_COMMIT();

        const uint32_t stb = sb + (kt % 3) * STG_B;
#pragma unroll
        for (int ks = 0; ks < 2; ++ks) {
            uint32_t ah[4][4];
#pragma unroll
            for (int mi = 0; mi < 4; ++mi)
                ldsm4a(ah[mi], stb + abase + mi * (16 * GRS) + ks * 32);
#pragma unroll
            for (int njp = 0; njp < 4; ++njp) {
                uint32_t b0, b1, b2, b3;
                LDSM4(b0, b1, b2, b3, stb + bbase + njp * (16 * GRS) + ks * 32);
                uint32_t bA[2] = {b0, b1}, bB[2] = {b2, b3};
#pragma unroll
                for (int mi = 0; mi < 4; ++mi) {
                    mma16816(c[mi][2 * njp],     ah[mi], bA);
                    mma16816(c[mi][2 * njp + 1], ah[mi], bB);
                }
            }
        }
    }

    // epilogue (MODE 0: part constant per CTA since 128 | 1024)
#pragma unroll
    for (int mi = 0; mi < 4; ++mi) {
        const int r0 = bm + wm * 64 + mi * 16 + g;
        const int r1 = r0 + 8;
#pragma unroll
        for (int nj = 0; nj < 8; ++nj) {
            const int cn = bn + wn * 64 + nj * 8 + 2 * t;
            if (MODE == 0) {
                const int part = bn >> 10, hh = (cn >> 6) & 15, dd = cn & 63;
                const int bb = r0 >> 11;
                const int tt0 = r0 & 2047, tt1 = r1 & 2047;
                if (part == 2) {
                    const size_t vb = ((size_t)((bb * H_ + hh) * HD_) + dd) * T_;
                    g_Vth[vb + tt0]      = __float2half_rn(c[mi][nj][0]);
                    g_Vth[vb + T_ + tt0] = __float2half_rn(c[mi][nj][1]);
                    g_Vth[vb + tt1]      = __float2half_rn(c[mi][nj][2]);
                    g_Vth[vb + T_ + tt1] = __float2half_rn(c[mi][nj][3]);
                } else {
                    const size_t o0 = (((size_t)(bb * H_ + hh) * T_ + tt0) << 6) + dd;
                    const size_t o1 = (((size_t)(bb * H_ + hh) * T_ + tt1) << 6) + dd;
                    if (part == 0) {
                        *(uint32_t*)(g_Qh + o0) = pack2h(c[mi][nj][0] * SC_Q, c[mi][nj][1] * SC_Q);
                        *(uint32_t*)(g_Qh + o1) = pack2h(c[mi][nj][2] * SC_Q, c[mi][nj][3] * SC_Q);
                    } else {
                        *(uint32_t*)(g_Kh + o0) = pack2h(c[mi][nj][0], c[mi][nj][1]);
                        *(uint32_t*)(g_Kh + o1) = pack2h(c[mi][nj][2], c[mi][nj][3]);
                    }
                }
            } else {
                float2 bv = *(const float2*)&bias[cn];
                *(float2*)&Cout[(size_t)r0 * D_ + cn] =
                    make_float2(c[mi][nj][0] + bv.x, c[mi][nj][1] + bv.y);
                *(float2*)&Cout[(size_t)r1 * D_ + cn] =
                    make_float2(c[mi][nj][2] + bv.x, c[mi][nj][3] + bv.y);
            }
        }
    }
}

// =====================================================================
// HMMA flash attention, causal. q-tile 64, 4 warps, LPT order.
// QK 1-term Qh*Kh (Q pre-scaled, log2 units); P fp16; PV 1-term Ph*Vh;
// row-sum l via all-ones MMA column.  O written fp16 (1-term proj).
// smem: 2 KV stages of [Kh|Vth], 64 rows x 144B each.
// =====================================================================
constexpr int KSTG = 2 * 64 * 144;        // 18432
constexpr int FA_SMEM = 2 * KSTG;         // 36864

__global__ __launch_bounds__(128, 3)
void flash_mma()
{
    extern __shared__ __align__(16) char sma[];
    const uint32_t sb = smem_u32(sma);
    const int tid = threadIdx.x, lane = tid & 31, wid = tid >> 5;
    const int g = lane >> 2, t = lane & 3;
    const int qt = gridDim.x - 1 - blockIdx.x;   // LPT: longest CTAs first
    const int bh = blockIdx.y;
    const int qbase = qt * 64;
    const int nkt = qt + 1;

    const size_t hb = (size_t)bh * T_ * HD_;
    const __half* Qhp = g_Qh + hb;
    const __half* Khp = g_Kh + hb;
    const __half* Vhp = g_Vth + hb;

    const float NEG_INF = __int_as_float(0xff800000);

    // ---- stage Q, hoist fragments ----
#pragma unroll
    for (int u = 0; u < 4; ++u) {
        int cidx = u * 128 + tid;
        int row = (cidx >> 3) & 63, ch = cidx & 7;
        cp16(sb + row * 144 + ch * 16, Qhp + (size_t)(qbase + row) * HD_ + ch * 8);
    }
    CP_COMMIT(); CP_WAIT0(); __syncthreads();

    uint32_t qh[4][4];
    {
        const uint32_t qb = sb + (wid * 16 + (lane & 7) + (lane & 8)) * 144 + (lane >> 4) * 16;
#pragma unroll
        for (int ks = 0; ks < 4; ++ks) ldsm4a(qh[ks], qb + ks * 32);
    }
    __syncthreads();

    auto issueKV = [&](int s, int kt) {
        const int ktb = kt * 64;
#pragma unroll
        for (int u = 0; u < 8; ++u) {
            int cidx = u * 128 + tid;
            int arr = cidx >> 9, row = (cidx >> 3) & 63, ch = cidx & 7;
            uint32_t dst = sb + s * KSTG + arr * 9216 + row * 144 + ch * 16;
            const __half* src = (arr == 0)
                ? Khp + (size_t)(ktb + row) * HD_ + ch * 8
                : Vhp + (size_t)row * T_ + ktb + ch * 8;
            cp16(dst, src);
        }
    };

    float cO[8][4];
#pragma unroll
    for (int j = 0; j < 8; ++j)
#pragma unroll
        for (int k = 0; k < 4; ++k) cO[j][k] = 0.f;
    float mrow[2] = {NEG_INF, NEG_INF};
    float lrow[2] = {0.f, 0.f};

    issueKV(0, 0); CP_COMMIT();

    const uint32_t frow = (uint32_t)(((lane & 7) + ((lane >> 1) & 8)) * 144 + (lane & 8) * 2);
    const uint32_t ones2 = 0x3C003C00u;
    const uint32_t onesb[2] = {ones2, ones2};

    for (int kt = 0; kt < nkt; ++kt) {
        CP_WAIT0();
        __syncthreads();
        if (kt + 1 < nkt) issueKV((kt + 1) & 1, kt + 1);
        CP_COMMIT();

        const uint32_t stb = sb + (kt & 1) * KSTG;

        // ---- S = Q K^T (1-term; log2 units) ----
        float cS[8][4];
#pragma unroll
        for (int j = 0; j < 8; ++j)
#pragma unroll
            for (int k = 0; k < 4; ++k) cS[j][k] = 0.f;

        const uint32_t kb = stb + frow;
#pragma unroll
        for (int ks = 0; ks < 4; ++ks) {
#pragma unroll
            for (int njp = 0; njp < 4; ++njp) {
                uint32_t b0, b1, b2, b3;
                LDSM4(b0, b1, b2, b3, kb + njp * 2304 + ks * 32);
                uint32_t bA[2] = {b0, b1}, bB[2] = {b2, b3};
                mma16816(cS[2 * njp], qh[ks], bA);
                mma16816(cS[2 * njp + 1], qh[ks], bB);
            }
        }

        // ---- causal mask (diagonal tile only) ----
        if (kt == nkt - 1) {
            const int kb0 = kt * 64;
#pragma unroll
            for (int h = 0; h < 2; ++h) {
                const int qrow = qbase + wid * 16 + g + 8 * h;
#pragma unroll
                for (int nj = 0; nj < 8; ++nj)
#pragma unroll
                    for (int cc = 0; cc < 2; ++cc)
                        if (kb0 + nj * 8 + 2 * t + cc > qrow) cS[nj][2 * h + cc] = NEG_INF;
            }
        }

        // ---- online softmax: f32 EX2, pack to fp16 P ----
        uint32_t pH[2][8];
#pragma unroll
        for (int h = 0; h < 2; ++h) {
            float mloc = NEG_INF;
#pragma unroll
            for (int nj = 0; nj < 8; ++nj)
                mloc = fmaxf(mloc, fmaxf(cS[nj][2 * h], cS[nj][2 * h + 1]));
            mloc = fmaxf(mloc, __shfl_xor_sync(0xffffffffu, mloc, 1));
            mloc = fmaxf(mloc, __shfl_xor_sync(0xffffffffu, mloc, 2));
            const float mnew  = fmaxf(mrow[h], mloc);
            const float alpha = ex2f(mrow[h] - mnew);
            mrow[h] = mnew;
#pragma unroll
            for (int nj = 0; nj < 8; ++nj) {
                float p0 = ex2f(cS[nj][2 * h]     - mnew);
                float p1 = ex2f(cS[nj][2 * h + 1] - mnew);
                pH[h][nj] = pack2h(p0, p1);
            }
            lrow[h] *= alpha;
#pragma unroll
            for (int nj = 0; nj < 8; ++nj) {
                cO[nj][2 * h + 0] *= alpha;
                cO[nj][2 * h + 1] *= alpha;
            }
        }

        // ---- O += P Vh; l += P * ones ----
        float cL[4] = {0.f, 0.f, 0.f, 0.f};
        const uint32_t vbh = stb + 9216 + frow;
#pragma unroll
        for (int ks = 0; ks < 4; ++ks) {
            uint32_t aP[4] = {pH[0][2 * ks], pH[1][2 * ks],
                              pH[0][2 * ks + 1], pH[1][2 * ks + 1]};
            mma16816(cL, aP, onesb);
#pragma unroll
            for (int njp = 0; njp < 4; ++njp) {
                uint32_t v0, v1, v2, v3;
                LDSM4(v0, v1, v2, v3, vbh + njp * 2304 + ks * 32);
                uint32_t vA[2] = {v0, v1}, vB[2] = {v2, v3};
                mma16816(cO[2 * njp], aP, vA);
                mma16816(cO[2 * njp + 1], aP, vB);
            }
        }
        lrow[0] += cL[0];
        lrow[1] += cL[2];
    }

    // ---- epilogue: normalize, fp16 O for 1-term proj ----
    const float i0 = 1.f / lrow[0];
    const float i1 = 1.f / lrow[1];
    const int q0 = qbase + wid * 16 + g;
    const int b = bh >> 4, hh = bh & 15;
    const size_t o0 = (size_t)(b * T_ + q0) * D_ + hh * 64 + 2 * t;
    const size_t o1 = o0 + (size_t)8 * D_;
#pragma unroll
    for (int nj = 0; nj < 8; ++nj) {
        *(uint32_t*)(g_Oh + o0 + nj * 8) = pack2h(cO[nj][0] * i0, cO[nj][1] * i0);
        *(uint32_t*)(g_Oh + o1 + nj * 8) = pack2h(cO[nj][2] * i1, cO[nj][3] * i1);
    }
}

// =====================================================================
extern "C" void kernel_launch(void* const* d_in, const int* in_sizes, int n_in,
                              void* d_out, int out_size)
{
    const float* x     = (const float*)d_in[0];
    const float* Wqkv  = (const float*)d_in[1];
    const float* Wproj = (const float*)d_in[2];
    const float* bproj = (const float*)d_in[3];
    float* out = (float*)d_out;
    (void)in_sizes; (void)n_in; (void)out_size;

    cudaFuncSetAttribute(gemm_mma<0>, cudaFuncAttributeMaxDynamicSharedMemorySize, G_SMEM);
    cudaFuncSetAttribute(gemm_mma<1>, cudaFuncAttributeMaxDynamicSharedMemorySize, G_SMEM);
    cudaFuncSetAttribute(flash_mma,   cudaFuncAttributeMaxDynamicSharedMemorySize, FA_SMEM);

    convert_in<<<(unsigned)((CX + CQ + CP) / 256), 256>>>(x, Wqkv, Wproj);

    dim3 gq(N_QKV / 128, M1 / 128);   // 24 x 64
    gemm_mma<0><<<gq, 128, G_SMEM>>>(nullptr, nullptr);

    dim3 ga(T_ / 64, B_ * H_);        // 32 x 64
    flash_mma<<<ga, 128, FA_SMEM>>>();

    dim3 gp(D_ / 128, M1 / 128);      // 8 x 64
    gemm_mma<1><<<gp, 128, G_SMEM>>>(bproj, out);
}

// round 15
// speedup vs baseline: 7.2792x; 1.0483x over previous
#include <cuda_runtime.h>
#include <cuda_fp16.h>
#include <cstdint>

#define DEVINLINE __device__ __forceinline__

constexpr int B_  = 4;
constexpr int T_  = 2048;
constexpr int D_  = 1024;
constexpr int H_  = 16;
constexpr int HD_ = 64;
constexpr int M1  = B_ * T_;              // 8192
constexpr int N_QKV = 3 * D_;             // 3072
constexpr size_t NE = (size_t)M1 * D_;    // 8388608

// ---- scratch (static __device__; no allocation allowed) ----
__device__ __half g_xh[NE];
__device__ __half g_wqh[(size_t)N_QKV * D_];
__device__ __half g_wph[(size_t)D_ * D_];
__device__ __half g_Qh[NE], g_Kh[NE];
__device__ __half g_Vth[NE];
__device__ __half g_Oh[NE];

// =====================================================================
// helpers (arch-portable PTX only: mma.sync/ldmatrix/cp.async)
// =====================================================================
DEVINLINE uint32_t smem_u32(const void* p) {
    uint32_t a;
    asm("{ .reg .u64 t; cvta.to.shared.u64 t, %1; cvt.u32.u64 %0, t; }" : "=r"(a) : "l"(p));
    return a;
}
DEVINLINE float ex2f(float x) {
    float y; asm("ex2.approx.ftz.f32 %0, %1;" : "=f"(y) : "f"(x)); return y;
}
DEVINLINE uint32_t pack2h(float x, float y) {
    __half2 h = __floats2half2_rn(x, y);
    return *reinterpret_cast<uint32_t*>(&h);
}
DEVINLINE void mma16816(float c[4], const uint32_t a[4], const uint32_t b[2]) {
    asm volatile(
        "mma.sync.aligned.m16n8k16.row.col.f32.f16.f16.f32 "
        "{%0,%1,%2,%3}, {%4,%5,%6,%7}, {%8,%9}, {%0,%1,%2,%3};"
        : "+f"(c[0]), "+f"(c[1]), "+f"(c[2]), "+f"(c[3])
        : "r"(a[0]), "r"(a[1]), "r"(a[2]), "r"(a[3]), "r"(b[0]), "r"(b[1]));
}
#define LDSM4(r0, r1, r2, r3, addr)                                           \
    asm volatile("ldmatrix.sync.aligned.m8n8.x4.shared.b16 {%0,%1,%2,%3}, [%4];" \
        : "=r"(r0), "=r"(r1), "=r"(r2), "=r"(r3) : "r"(addr))
DEVINLINE void ldsm4a(uint32_t r[4], uint32_t addr) { LDSM4(r[0], r[1], r[2], r[3], addr); }
DEVINLINE void cp16(uint32_t dst, const void* src) {
    asm volatile("cp.async.cg.shared.global [%0], [%1], 16;" :: "r"(dst), "l"(src));
}
#define CP_COMMIT() asm volatile("cp.async.commit_group;" ::: "memory")
#define CP_WAIT0()  asm volatile("cp.async.wait_group 0;" ::: "memory")
#define CP_WAIT1()  asm volatile("cp.async.wait_group 1;" ::: "memory")

// =====================================================================
// convert inputs: x -> hi fp16; W_qkv, W_proj -> hi fp16
// =====================================================================
constexpr size_t CX = NE / 4;
constexpr size_t CQ = (size_t)N_QKV * D_ / 4;
constexpr size_t CP = (size_t)D_ * D_ / 4;
__global__ void convert_in(const float* __restrict__ x, const float* __restrict__ wq,
                           const float* __restrict__ wp)
{
    size_t i = (size_t)blockIdx.x * 256 + threadIdx.x;
    if (i < CX) {
        float4 v = ((const float4*)x)[i];
        ((uint2*)g_xh)[i] = make_uint2(pack2h(v.x, v.y), pack2h(v.z, v.w));
    } else if (i < CX + CQ) {
        size_t j = i - CX;
        float4 v = ((const float4*)wq)[j];
        ((uint2*)g_wqh)[j] = make_uint2(pack2h(v.x, v.y), pack2h(v.z, v.w));
    } else {
        size_t j = i - CX - CQ;
        float4 v = ((const float4*)wp)[j];
        ((uint2*)g_wph)[j] = make_uint2(pack2h(v.x, v.y), pack2h(v.z, v.w));
    }
}

// =====================================================================
// HMMA GEMM, 1-term. CTA tile BM(M)x128(N), 4 warps (warp BM/2 x 64),
// K-stage 32, 3-stage cp.async, ldmatrix.
// MODE 0 (BM=128, 3 CTAs/SM): x*Wqkv -> Q (pre-scaled) / K / V(transposed).
// MODE 1 (BM=64, 4 CTAs/SM):  Oh*Wproj + bias -> out (f32).
// =====================================================================
constexpr int GRS = 80;                    // smem row stride bytes (64B + 16 pad)
constexpr float SC_Q = 0.18033688011112042385f;   // log2(e)/sqrt(64)

template <int MODE, int BM>
__global__ __launch_bounds__(128, (MODE == 0 ? 3 : 4))
void gemm_mma(const float* __restrict__ bias, float* __restrict__ Cout)
{
    constexpr int ASTG  = BM * GRS;
    constexpr int STG_B = (BM + 128) * GRS;
    constexpr int MI    = BM / 32;
    constexpr int AOPS  = BM * 4;

    extern __shared__ __align__(16) char smg[];
    const uint32_t sb = smem_u32(smg);
    const __half* Ah = (MODE == 0) ? g_xh : g_Oh;
    const __half* Bh = (MODE == 0) ? g_wqh : g_wph;

    const int tid = threadIdx.x, lane = tid & 31, wid = tid >> 5;
    const int g = lane >> 2, t = lane & 3;
    const int wm = wid & 1, wn = wid >> 1;
    const int bm = blockIdx.y * BM, bn = blockIdx.x * 128;

    float c[MI][8][4];
#pragma unroll
    for (int i = 0; i < MI; ++i)
#pragma unroll
        for (int j = 0; j < 8; ++j)
#pragma unroll
            for (int k = 0; k < 4; ++k) c[i][j][k] = 0.f;

    auto issue = [&](int s, int kt) {
        const uint32_t st = sb + s * STG_B;
        const int k0 = kt * 32;
#pragma unroll
        for (int u = 0; u < (BM + 128) / 32; ++u) {
            int idx = u * 128 + tid;
            if (idx < AOPS) {
                int row = idx >> 2, ch = idx & 3;
                cp16(st + row * GRS + ch * 16,
                     Ah + (size_t)(bm + row) * D_ + k0 + ch * 8);
            } else {
                int j = idx - AOPS;
                int row = j >> 2, ch = j & 3;
                cp16(st + ASTG + row * GRS + ch * 16,
                     Bh + (size_t)(bn + row) * D_ + k0 + ch * 8);
            }
        }
    };

    const uint32_t abase = (uint32_t)((wm * (BM / 2) + (lane & 7) + (lane & 8)) * GRS + (lane >> 4) * 16);
    const uint32_t bbase = (uint32_t)(ASTG + (wn * 64 + (lane & 7) + ((lane >> 1) & 8)) * GRS + (lane & 8) * 2);

    issue(0, 0); CP_COMMIT();
    issue(1, 1); CP_COMMIT();

    constexpr int NT = D_ / 32;   // 32
    for (int kt = 0; kt < NT; ++kt) {
        CP_WAIT1();
        __syncthreads();
        if (kt + 2 < NT) issue((kt + 2) % 3, kt + 2);
        CP_COMMIT();

        const uint32_t stb = sb + (kt % 3) * STG_B;
#pragma unroll
        for (int ks = 0; ks < 2; ++ks) {
            uint32_t ah[MI][4];
#pragma unroll
            for (int mi = 0; mi < MI; ++mi)
                ldsm4a(ah[mi], stb + abase + mi * (16 * GRS) + ks * 32);
#pragma unroll
            for (int njp = 0; njp < 4; ++njp) {
                uint32_t b0, b1, b2, b3;
                LDSM4(b0, b1, b2, b3, stb + bbase + njp * (16 * GRS) + ks * 32);
                uint32_t bA[2] = {b0, b1}, bB[2] = {b2, b3};
#pragma unroll
                for (int mi = 0; mi < MI; ++mi) {
                    mma16816(c[mi][2 * njp],     ah[mi], bA);
                    mma16816(c[mi][2 * njp + 1], ah[mi], bB);
                }
            }
        }
    }

    // epilogue (MODE 0: part constant per CTA since 128 | 1024)
#pragma unroll
    for (int mi = 0; mi < MI; ++mi) {
        const int r0 = bm + wm * (BM / 2) + mi * 16 + g;
        const int r1 = r0 + 8;
#pragma unroll
        for (int nj = 0; nj < 8; ++nj) {
            const int cn = bn + wn * 64 + nj * 8 + 2 * t;
            if (MODE == 0) {
                const int part = bn >> 10, hh = (cn >> 6) & 15, dd = cn & 63;
                const int bb = r0 >> 11;
                const int tt0 = r0 & 2047, tt1 = r1 & 2047;
                if (part == 2) {
                    const size_t vb = ((size_t)((bb * H_ + hh) * HD_) + dd) * T_;
                    g_Vth[vb + tt0]      = __float2half_rn(c[mi][nj][0]);
                    g_Vth[vb + T_ + tt0] = __float2half_rn(c[mi][nj][1]);
                    g_Vth[vb + tt1]      = __float2half_rn(c[mi][nj][2]);
                    g_Vth[vb + T_ + tt1] = __float2half_rn(c[mi][nj][3]);
                } else {
                    const size_t o0 = (((size_t)(bb * H_ + hh) * T_ + tt0) << 6) + dd;
                    const size_t o1 = (((size_t)(bb * H_ + hh) * T_ + tt1) << 6) + dd;
                    if (part == 0) {
                        *(uint32_t*)(g_Qh + o0) = pack2h(c[mi][nj][0] * SC_Q, c[mi][nj][1] * SC_Q);
                        *(uint32_t*)(g_Qh + o1) = pack2h(c[mi][nj][2] * SC_Q, c[mi][nj][3] * SC_Q);
                    } else {
                        *(uint32_t*)(g_Kh + o0) = pack2h(c[mi][nj][0], c[mi][nj][1]);
                        *(uint32_t*)(g_Kh + o1) = pack2h(c[mi][nj][2], c[mi][nj][3]);
                    }
                }
            } else {
                float2 bv = *(const float2*)&bias[cn];
                *(float2*)&Cout[(size_t)r0 * D_ + cn] =
                    make_float2(c[mi][nj][0] + bv.x, c[mi][nj][1] + bv.y);
                *(float2*)&Cout[(size_t)r1 * D_ + cn] =
                    make_float2(c[mi][nj][2] + bv.x, c[mi][nj][3] + bv.y);
            }
        }
    }
}

// =====================================================================
// HMMA flash attention, causal. q-tile 64, 4 warps, LPT order.
// QK 1-term Qh*Kh (Q pre-scaled, log2 units); P fp16; PV 1-term Ph*Vh;
// row-sum l via all-ones MMA column; alpha-rescale skipped by warp vote
// when no row's max updated.  O written fp16 (1-term proj).
// smem: 2 KV stages of [Kh|Vth], 64 rows x 144B each.
// =====================================================================
constexpr int KSTG = 2 * 64 * 144;        // 18432
constexpr int FA_SMEM = 2 * KSTG;         // 36864

__global__ __launch_bounds__(128, 3)
void flash_mma()
{
    extern __shared__ __align__(16) char sma[];
    const uint32_t sb = smem_u32(sma);
    const int tid = threadIdx.x, lane = tid & 31, wid = tid >> 5;
    const int g = lane >> 2, t = lane & 3;
    const int qt = gridDim.x - 1 - blockIdx.x;   // LPT: longest CTAs first
    const int bh = blockIdx.y;
    const int qbase = qt * 64;
    const int nkt = qt + 1;

    const size_t hb = (size_t)bh * T_ * HD_;
    const __half* Qhp = g_Qh + hb;
    const __half* Khp = g_Kh + hb;
    const __half* Vhp = g_Vth + hb;

    const float NEG_INF = __int_as_float(0xff800000);

    // ---- stage Q, hoist fragments ----
#pragma unroll
    for (int u = 0; u < 4; ++u) {
        int cidx = u * 128 + tid;
        int row = (cidx >> 3) & 63, ch = cidx & 7;
        cp16(sb + row * 144 + ch * 16, Qhp + (size_t)(qbase + row) * HD_ + ch * 8);
    }
    CP_COMMIT(); CP_WAIT0(); __syncthreads();

    uint32_t qh[4][4];
    {
        const uint32_t qb = sb + (wid * 16 + (lane & 7) + (lane & 8)) * 144 + (lane >> 4) * 16;
#pragma unroll
        for (int ks = 0; ks < 4; ++ks) ldsm4a(qh[ks], qb + ks * 32);
    }
    __syncthreads();

    auto issueKV = [&](int s, int kt) {
        const int ktb = kt * 64;
#pragma unroll
        for (int u = 0; u < 8; ++u) {
            int cidx = u * 128 + tid;
            int arr = cidx >> 9, row = (cidx >> 3) & 63, ch = cidx & 7;
            uint32_t dst = sb + s * KSTG + arr * 9216 + row * 144 + ch * 16;
            const __half* src = (arr == 0)
                ? Khp + (size_t)(ktb + row) * HD_ + ch * 8
                : Vhp + (size_t)row * T_ + ktb + ch * 8;
            cp16(dst, src);
        }
    };

    float cO[8][4];
#pragma unroll
    for (int j = 0; j < 8; ++j)
#pragma unroll
        for (int k = 0; k < 4; ++k) cO[j][k] = 0.f;
    float mrow[2] = {NEG_INF, NEG_INF};
    float lrow[2] = {0.f, 0.f};

    issueKV(0, 0); CP_COMMIT();

    const uint32_t frow = (uint32_t)(((lane & 7) + ((lane >> 1) & 8)) * 144 + (lane & 8) * 2);
    const uint32_t ones2 = 0x3C003C00u;
    const uint32_t onesb[2] = {ones2, ones2};

    for (int kt = 0; kt < nkt; ++kt) {
        CP_WAIT0();
        __syncthreads();
        if (kt + 1 < nkt) issueKV((kt + 1) & 1, kt + 1);
        CP_COMMIT();

        const uint32_t stb = sb + (kt & 1) * KSTG;

        // ---- S = Q K^T (1-term; log2 units) ----
        float cS[8][4];
#pragma unroll
        for (int j = 0; j < 8; ++j)
#pragma unroll
            for (int k = 0; k < 4; ++k) cS[j][k] = 0.f;

        const uint32_t kb = stb + frow;
#pragma unroll
        for (int ks = 0; ks < 4; ++ks) {
#pragma unroll
            for (int njp = 0; njp < 4; ++njp) {
                uint32_t b0, b1, b2, b3;
                LDSM4(b0, b1, b2, b3, kb + njp * 2304 + ks * 32);
                uint32_t bA[2] = {b0, b1}, bB[2] = {b2, b3};
                mma16816(cS[2 * njp], qh[ks], bA);
                mma16816(cS[2 * njp + 1], qh[ks], bB);
            }
        }

        // ---- causal mask (diagonal tile only) ----
        if (kt == nkt - 1) {
            const int kb0 = kt * 64;
#pragma unroll
            for (int h = 0; h < 2; ++h) {
                const int qrow = qbase + wid * 16 + g + 8 * h;
#pragma unroll
                for (int nj = 0; nj < 8; ++nj)
#pragma unroll
                    for (int cc = 0; cc < 2; ++cc)
                        if (kb0 + nj * 8 + 2 * t + cc > qrow) cS[nj][2 * h + cc] = NEG_INF;
            }
        }

        // ---- online softmax: f32 EX2, pack to fp16 P; vote-skip rescale ----
        uint32_t pH[2][8];
#pragma unroll
        for (int h = 0; h < 2; ++h) {
            float mloc = NEG_INF;
#pragma unroll
            for (int nj = 0; nj < 8; ++nj)
                mloc = fmaxf(mloc, fmaxf(cS[nj][2 * h], cS[nj][2 * h + 1]));
            mloc = fmaxf(mloc, __shfl_xor_sync(0xffffffffu, mloc, 1));
            mloc = fmaxf(mloc, __shfl_xor_sync(0xffffffffu, mloc, 2));
            const float mnew = fmaxf(mrow[h], mloc);
            if (__any_sync(0xffffffffu, mnew != mrow[h])) {
                const float alpha = ex2f(mrow[h] - mnew);
                lrow[h] *= alpha;
#pragma unroll
                for (int nj = 0; nj < 8; ++nj) {
                    cO[nj][2 * h + 0] *= alpha;
                    cO[nj][2 * h + 1] *= alpha;
                }
                mrow[h] = mnew;
            }
#pragma unroll
            for (int nj = 0; nj < 8; ++nj) {
                float p0 = ex2f(cS[nj][2 * h]     - mrow[h]);
                float p1 = ex2f(cS[nj][2 * h + 1] - mrow[h]);
                pH[h][nj] = pack2h(p0, p1);
            }
        }

        // ---- O += P Vh; l += P * ones ----
        float cL[4] = {0.f, 0.f, 0.f, 0.f};
        const uint32_t vbh = stb + 9216 + frow;
#pragma unroll
        for (int ks = 0; ks < 4; ++ks) {
            uint32_t aP[4] = {pH[0][2 * ks], pH[1][2 * ks],
                              pH[0][2 * ks + 1], pH[1][2 * ks + 1]};
            mma16816(cL, aP, onesb);
#pragma unroll
            for (int njp = 0; njp < 4; ++njp) {
                uint32_t v0, v1, v2, v3;
                LDSM4(v0, v1, v2, v3, vbh + njp * 2304 + ks * 32);
                uint32_t vA[2] = {v0, v1}, vB[2] = {v2, v3};
                mma16816(cO[2 * njp], aP, vA);
                mma16816(cO[2 * njp + 1], aP, vB);
            }
        }
        lrow[0] += cL[0];
        lrow[1] += cL[2];
    }

    // ---- epilogue: normalize, fp16 O for 1-term proj ----
    const float i0 = 1.f / lrow[0];
    const float i1 = 1.f / lrow[1];
    const int q0 = qbase + wid * 16 + g;
    const int b = bh >> 4, hh = bh & 15;
    const size_t o0 = (size_t)(b * T_ + q0) * D_ + hh * 64 + 2 * t;
    const size_t o1 = o0 + (size_t)8 * D_;
#pragma unroll
    for (int nj = 0; nj < 8; ++nj) {
        *(uint32_t*)(g_Oh + o0 + nj * 8) = pack2h(cO[nj][0] * i0, cO[nj][1] * i0);
        *(uint32_t*)(g_Oh + o1 + nj * 8) = pack2h(cO[nj][2] * i1, cO[nj][3] * i1);
    }
}

// =====================================================================
extern "C" void kernel_launch(void* const* d_in, const int* in_sizes, int n_in,
                              void* d_out, int out_size)
{
    const float* x     = (const float*)d_in[0];
    const float* Wqkv  = (const float*)d_in[1];
    const float* Wproj = (const float*)d_in[2];
    const float* bproj = (const float*)d_in[3];
    float* out = (float*)d_out;
    (void)in_sizes; (void)n_in; (void)out_size;

    constexpr int G_SMEM0 = 3 * (256 * GRS);   // 61440
    constexpr int G_SMEM1 = 3 * (192 * GRS);   // 46080

    cudaFuncSetAttribute((const void*)gemm_mma<0, 128>,
                         cudaFuncAttributeMaxDynamicSharedMemorySize, G_SMEM0);
    cudaFuncSetAttribute((const void*)gemm_mma<1, 64>,
                         cudaFuncAttributeMaxDynamicSharedMemorySize, G_SMEM1);
    cudaFuncSetAttribute((const void*)flash_mma,
                         cudaFuncAttributeMaxDynamicSharedMemorySize, FA_SMEM);

    convert_in<<<(unsigned)((CX + CQ + CP) / 256), 256>>>(x, Wqkv, Wproj);

    dim3 gq(N_QKV / 128, M1 / 128);   // 24 x 64
    gemm_mma<0, 128><<<gq, 128, G_SMEM0>>>(nullptr, nullptr);

    dim3 ga(T_ / 64, B_ * H_);        // 32 x 64
    flash_mma<<<ga, 128, FA_SMEM>>>();

    dim3 gp(D_ / 128, M1 / 64);       // 8 x 128
    gemm_mma<1, 64><<<gp, 128, G_SMEM1>>>(bproj, out);
}